// round 12
// baseline (speedup 1.0000x reference)
#include <cuda_runtime.h>
#include <cuda_bf16.h>
#include <cuda_fp16.h>
#include <cstdint>

#define BB 8
#define CC 64
#define NN 4096
#define PITCH 68      // fp32 smem pitch (qkv ws / apply ws)
#define RPITCH 132    // fp32 pitch for apply res tile (128 n + pad)
#define BPITCH 144    // bf16/fp16 tile pitch bytes (64 elems + pad)
#define APITCH 272    // apply P-tile pitch bytes (128 fp16 + pad)

// ---------------- scratch ----------------
__device__ __nv_bfloat16 g_qh[BB*NN*CC], g_ql[BB*NN*CC];
__device__ __nv_bfloat16 g_kh[BB*NN*CC], g_kl[BB*NN*CC];
__device__ __half g_vf[BB*NN*CC];                   // V fp16 [b][j][c]
__device__ __half g_pf16[(size_t)BB*NN*NN];         // P~ fp16 [b][j][i-permuted]
__device__ float  g_em[(size_t)BB*64*NN];           // e^{m_t(j)} [b][t][j]
__device__ __half g_azh[(size_t)BB*64*NN];          // az = e^{m_t}/Z_j fp16 [b][t][j]

#define LD4(p) (*(const float4*)(p))

__device__ __forceinline__ uint32_t smem_to_u32(const void* p) {
    uint32_t a;
    asm("{ .reg .u64 t; cvta.to.shared.u64 t, %1; cvt.u32.u64 %0, t; }" : "=r"(a) : "l"(p));
    return a;
}
__device__ __forceinline__ void ldsm4(uint32_t addr, uint32_t* r) {
    asm volatile("ldmatrix.sync.aligned.m8n8.x4.shared.b16 {%0,%1,%2,%3}, [%4];"
                 : "=r"(r[0]), "=r"(r[1]), "=r"(r[2]), "=r"(r[3]) : "r"(addr));
}
__device__ __forceinline__ void ldsm4t(uint32_t addr, uint32_t* r) {
    asm volatile("ldmatrix.sync.aligned.m8n8.x4.trans.shared.b16 {%0,%1,%2,%3}, [%4];"
                 : "=r"(r[0]), "=r"(r[1]), "=r"(r[2]), "=r"(r[3]) : "r"(addr));
}
__device__ __forceinline__ void mma16816(float* c, const uint32_t* a, uint32_t b0, uint32_t b1) {
    asm volatile("mma.sync.aligned.m16n8k16.row.col.f32.bf16.bf16.f32 "
                 "{%0,%1,%2,%3}, {%4,%5,%6,%7}, {%8,%9}, {%0,%1,%2,%3};"
                 : "+f"(c[0]), "+f"(c[1]), "+f"(c[2]), "+f"(c[3])
                 : "r"(a[0]), "r"(a[1]), "r"(a[2]), "r"(a[3]), "r"(b0), "r"(b1));
}
__device__ __forceinline__ void mma16816h(float* c, const uint32_t* a, uint32_t b0, uint32_t b1) {
    asm volatile("mma.sync.aligned.m16n8k16.row.col.f32.f16.f16.f32 "
                 "{%0,%1,%2,%3}, {%4,%5,%6,%7}, {%8,%9}, {%0,%1,%2,%3};"
                 : "+f"(c[0]), "+f"(c[1]), "+f"(c[2]), "+f"(c[3])
                 : "r"(a[0]), "r"(a[1]), "r"(a[2]), "r"(a[3]), "r"(b0), "r"(b1));
}
__device__ __forceinline__ uint32_t packh2(float lo, float hi) {
    __half2 h = __floats2half2_rn(lo, hi);
    return *reinterpret_cast<uint32_t*>(&h);
}
__device__ __forceinline__ uint32_t hmul2u(uint32_t a, uint32_t b) {
    __half2 r = __hmul2(*reinterpret_cast<__half2*>(&a), *reinterpret_cast<__half2*>(&b));
    return *reinterpret_cast<uint32_t*>(&r);
}
__device__ __forceinline__ void split2(float p0, float p1, uint32_t& h, uint32_t& l) {
    __nv_bfloat16 h0 = __float2bfloat16_rn(p0), h1 = __float2bfloat16_rn(p1);
    __nv_bfloat16 l0 = __float2bfloat16_rn(p0 - __bfloat162float(h0));
    __nv_bfloat16 l1 = __float2bfloat16_rn(p1 - __bfloat162float(h1));
    h = ((uint32_t)__bfloat16_as_ushort(h1) << 16) | __bfloat16_as_ushort(h0);
    l = ((uint32_t)__bfloat16_as_ushort(l1) << 16) | __bfloat16_as_ushort(l0);
}
__device__ __forceinline__ void cp16(uint32_t saddr, const void* gaddr) {
    asm volatile("cp.async.cg.shared.global [%0], [%1], 16;" :: "r"(saddr), "l"(gaddr));
}
#define CP_COMMIT() asm volatile("cp.async.commit_group;" ::: "memory")
#define CP_WAIT0()  asm volatile("cp.async.wait_group 0;" ::: "memory")
#define CP_WAIT1()  asm volatile("cp.async.wait_group 1;" ::: "memory")

// A fragment m16k16 from [m][k] storage (pitch BPITCH)
__device__ __forceinline__ uint32_t addrA(uint32_t base, int r0, int c0, int lr, int g) {
    return base + (uint32_t)(r0 + lr + ((g & 1) << 3)) * BPITCH + ((uint32_t)(c0 + ((g >> 1) << 3)) << 1);
}
// B fragments from [n][k] storage
__device__ __forceinline__ uint32_t addrB(uint32_t base, int n0, int k0, int lr, int g) {
    return base + (uint32_t)(n0 + lr) * BPITCH + ((uint32_t)(k0 + g * 8) << 1);
}
// A fragment m16k16 via trans from [k][m] storage (pitch APITCH)
__device__ __forceinline__ uint32_t addrAt(uint32_t base, int m0, int k0, int lr, int g) {
    return base + (uint32_t)(k0 + ((g >> 1) << 3) + lr) * APITCH + ((uint32_t)(m0 + ((g & 1) << 3)) << 1);
}
// B fragments via trans from [k][n] storage (pitch BPITCH)
__device__ __forceinline__ uint32_t addrBt(uint32_t base, int k0, int n0, int lr, int g) {
    return base + (uint32_t)(k0 + g * 8 + lr) * BPITCH + ((uint32_t)n0 << 1);
}
// permutation: swap bits [4:3] <-> [2:1] (i within 64-tile; bit 6 preserved)
__device__ __forceinline__ int swapbits(int idx) {
    return (idx & 0x61) | ((idx & 0x18) >> 2) | ((idx & 0x06) << 2);
}

// ------------------------------------------------------------------
// Kernel 1: q,k -> bf16 hi/lo planes [b][n][c]; v -> fp16 [b][n][c]
// ------------------------------------------------------------------
__global__ void qkv_kernel(const float* __restrict__ x,
                           const float* __restrict__ Wq, const float* __restrict__ bq,
                           const float* __restrict__ Wk, const float* __restrict__ bk,
                           const float* __restrict__ Wv, const float* __restrict__ bv)
{
    extern __shared__ float smf[];
    float* ws = smf;
    float* xs = smf + 3*CC*PITCH;
    const int b  = blockIdx.y;
    const int n0 = blockIdx.x * 64;
    const int t  = threadIdx.x;

    const float* Wmats[3] = {Wq, Wk, Wv};
    #pragma unroll
    for (int m = 0; m < 3; m++)
        for (int idx = t; idx < CC*CC; idx += 256) {
            int cout = idx >> 6, cin = idx & 63;
            ws[(m*CC + cin)*PITCH + cout] = Wmats[m][idx];
        }
    for (int idx = t; idx < CC*64; idx += 256) {
        int cin = idx >> 6, n = idx & 63;
        xs[cin*64 + n] = x[(size_t)(b*CC + cin)*NN + n0 + n];
    }
    __syncthreads();

    const int tx = t & 15, ty = t >> 4;
    float acc[3][4][4];
    #pragma unroll
    for (int m = 0; m < 3; m++)
        #pragma unroll
        for (int k = 0; k < 4; k++)
            #pragma unroll
            for (int j = 0; j < 4; j++) acc[m][k][j] = 0.f;

    #pragma unroll 4
    for (int ci = 0; ci < CC; ci++) {
        float xv[4];
        #pragma unroll
        for (int k = 0; k < 4; k++) xv[k] = xs[ci*64 + ty + 16*k];
        #pragma unroll
        for (int m = 0; m < 3; m++) {
            const float4 w4 = LD4(&ws[(m*CC + ci)*PITCH + 4*tx]);
            #pragma unroll
            for (int k = 0; k < 4; k++) {
                acc[m][k][0] = fmaf(xv[k], w4.x, acc[m][k][0]);
                acc[m][k][1] = fmaf(xv[k], w4.y, acc[m][k][1]);
                acc[m][k][2] = fmaf(xv[k], w4.z, acc[m][k][2]);
                acc[m][k][3] = fmaf(xv[k], w4.w, acc[m][k][3]);
            }
        }
    }

    const float* biases[2] = {bq, bk};
    __nv_bfloat16* outsH[2] = {g_qh, g_kh};
    __nv_bfloat16* outsL[2] = {g_ql, g_kl};
    #pragma unroll
    for (int m = 0; m < 2; m++) {
        const float4 bb4 = LD4(&biases[m][4*tx]);
        const float bbv[4] = {bb4.x, bb4.y, bb4.z, bb4.w};
        #pragma unroll
        for (int k = 0; k < 4; k++) {
            int n = n0 + ty + 16*k;
            uint32_t Hp[2], Lp[2];
            #pragma unroll
            for (int jp = 0; jp < 2; jp++) {
                float v0 = acc[m][k][2*jp]   + bbv[2*jp];
                float v1 = acc[m][k][2*jp+1] + bbv[2*jp+1];
                split2(v0, v1, Hp[jp], Lp[jp]);
            }
            size_t idx = (size_t)(b*NN + n)*CC + 4*tx;
            *reinterpret_cast<uint2*>(&outsH[m][idx]) = make_uint2(Hp[0], Hp[1]);
            *reinterpret_cast<uint2*>(&outsL[m][idx]) = make_uint2(Lp[0], Lp[1]);
        }
    }
    {
        const float4 bb4 = LD4(&bv[4*tx]);
        #pragma unroll
        for (int k = 0; k < 4; k++) {
            int n = n0 + ty + 16*k;
            uint32_t u0 = packh2(acc[2][k][0] + bb4.x, acc[2][k][1] + bb4.y);
            uint32_t u1 = packh2(acc[2][k][2] + bb4.z, acc[2][k][3] + bb4.w);
            *reinterpret_cast<uint2*>(&g_vf[(size_t)(b*NN + n)*CC + 4*tx]) = make_uint2(u0, u1);
        }
    }
}

// ------------------------------------------------------------------
// Kernel 2: stats, K stage = 128 i-rows (2 subtiles per barrier window)
// grid (NN/128, BB), 256 thr.
// smem: Q 2x18432 @0, K 2 stages x 36864 @36864 (hi@+0, lo@+18432), zi @110592
// ------------------------------------------------------------------
#define ST_K    36864
#define ST_ZI   110592
#define ST_SMEM 111104

__global__ void __launch_bounds__(256) stats_kernel()
{
    extern __shared__ char smc[];
    const uint32_t sb = smem_to_u32(smc);
    float* szi = reinterpret_cast<float*>(smc + ST_ZI);
    const int b = blockIdx.y, j0 = blockIdx.x * 128;
    const int t = threadIdx.x, w = t >> 5, lane = t & 31;
    const int lr = lane & 7, g = lane >> 3, qr = lane >> 2, qc = lane & 3;

    // prefetch K stages 0,1 (128 rows each)
    #pragma unroll
    for (int pf = 0; pf < 2; pf++) {
        const uint32_t dH = sb + ST_K + pf*36864, dL = dH + 18432;
        const int i0n = pf * 128;
        #pragma unroll
        for (int p = 0; p < 4; p++) {
            int idx = t + p*256; int row = idx >> 3, seg = idx & 7;
            cp16(dH + row*BPITCH + seg*16, &g_kh[(size_t)(b*NN + i0n + row)*CC + seg*8]);
            cp16(dL + row*BPITCH + seg*16, &g_kl[(size_t)(b*NN + i0n + row)*CC + seg*8]);
        }
        CP_COMMIT();
    }

    {   // Q tiles (128 rows, plain loads)
        const __nv_bfloat16* sH = &g_qh[(size_t)(b*NN + j0)*CC];
        const __nv_bfloat16* sL = &g_ql[(size_t)(b*NN + j0)*CC];
        for (int idx = t; idx < 1024; idx += 256) {
            int row = idx >> 3, seg = idx & 7;
            *(uint4*)(smc + row*BPITCH + seg*16)         = *(const uint4*)&sH[row*64 + seg*8];
            *(uint4*)(smc + 18432 + row*BPITCH + seg*16) = *(const uint4*)&sL[row*64 + seg*8];
        }
    }
    __syncthreads();

    uint32_t Ah[4][4], Al[4][4];
    #pragma unroll
    for (int ks = 0; ks < 4; ks++) {
        ldsm4(addrA(sb,         w*16, ks*16, lr, g), Ah[ks]);
        ldsm4(addrA(sb + 18432, w*16, ks*16, lr, g), Al[ks]);
    }

    float zacc0 = 0.f, zacc1 = 0.f;
    const int jlo = j0 + w*16 + qr;
    const int NST = NN/128;   // 32 stages of 128 i-rows  (R11 bug: was NN/256)

    for (int st = 0; st < NST; st++) {
        if (st < NST - 1) CP_WAIT1(); else CP_WAIT0();
        __syncthreads();

        const uint32_t kbH = sb + ST_K + (st & 1)*36864, kbL = kbH + 18432;

        #pragma unroll
        for (int sub = 0; sub < 2; sub++) {
            const int it = st*2 + sub;
            const int n0s = sub*64;
            float C[8][4];
            #pragma unroll
            for (int nt = 0; nt < 8; nt++) {
                uint32_t bh[8], bl[8];
                ldsm4(addrB(kbH, n0s + nt*8,  0, lr, g), bh);
                ldsm4(addrB(kbH, n0s + nt*8, 32, lr, g), bh + 4);
                ldsm4(addrB(kbL, n0s + nt*8,  0, lr, g), bl);
                ldsm4(addrB(kbL, n0s + nt*8, 32, lr, g), bl + 4);
                C[nt][0] = C[nt][1] = C[nt][2] = C[nt][3] = 0.f;
                #pragma unroll
                for (int ks = 0; ks < 4; ks++) mma16816(C[nt], Ah[ks], bh[2*ks], bh[2*ks+1]);
                #pragma unroll
                for (int ks = 0; ks < 4; ks++) mma16816(C[nt], Ah[ks], bl[2*ks], bl[2*ks+1]);
                #pragma unroll
                for (int ks = 0; ks < 4; ks++) mma16816(C[nt], Al[ks], bh[2*ks], bh[2*ks+1]);
            }

            float pm0 = C[0][0], pm1 = C[0][2];
            #pragma unroll
            for (int nt = 0; nt < 8; nt++) {
                pm0 = fmaxf(pm0, fmaxf(C[nt][0], C[nt][1]));
                pm1 = fmaxf(pm1, fmaxf(C[nt][2], C[nt][3]));
            }
            pm0 = fmaxf(pm0, __shfl_xor_sync(0xffffffffu, pm0, 1));
            pm0 = fmaxf(pm0, __shfl_xor_sync(0xffffffffu, pm0, 2));
            pm1 = fmaxf(pm1, __shfl_xor_sync(0xffffffffu, pm1, 1));
            pm1 = fmaxf(pm1, __shfl_xor_sync(0xffffffffu, pm1, 2));
            const float em0 = __expf(pm0), em1 = __expf(pm1);

            float ps0 = 0.f, ps1 = 0.f;
            #pragma unroll
            for (int nt = 0; nt < 8; nt++) {
                C[nt][0] = __expf(C[nt][0] - pm0);
                C[nt][1] = __expf(C[nt][1] - pm0);
                C[nt][2] = __expf(C[nt][2] - pm1);
                C[nt][3] = __expf(C[nt][3] - pm1);
                ps0 += C[nt][0] + C[nt][1];
                ps1 += C[nt][2] + C[nt][3];
            }
            ps0 += __shfl_xor_sync(0xffffffffu, ps0, 1);
            ps0 += __shfl_xor_sync(0xffffffffu, ps0, 2);
            ps1 += __shfl_xor_sync(0xffffffffu, ps1, 1);
            ps1 += __shfl_xor_sync(0xffffffffu, ps1, 2);
            zacc0 += em0 * ps0;
            zacc1 += em1 * ps1;

            // coalesced permuted store
            const size_t rb0 = (size_t)(b*NN + jlo)*NN + it*64;
            const size_t rb1 = rb0 + (size_t)8*NN;
            #pragma unroll
            for (int pk = 0; pk < 2; pk++) {
                uint4 u0, u1;
                u0.x = packh2(C[pk*4+0][0], C[pk*4+0][1]);
                u0.y = packh2(C[pk*4+1][0], C[pk*4+1][1]);
                u0.z = packh2(C[pk*4+2][0], C[pk*4+2][1]);
                u0.w = packh2(C[pk*4+3][0], C[pk*4+3][1]);
                u1.x = packh2(C[pk*4+0][2], C[pk*4+0][3]);
                u1.y = packh2(C[pk*4+1][2], C[pk*4+1][3]);
                u1.z = packh2(C[pk*4+2][2], C[pk*4+2][3]);
                u1.w = packh2(C[pk*4+3][2], C[pk*4+3][3]);
                *(uint4*)&g_pf16[rb0 + pk*32 + qc*8] = u0;
                *(uint4*)&g_pf16[rb1 + pk*32 + qc*8] = u1;
            }
            if (qc == 0) {
                g_em[(size_t)(b*64 + it)*NN + jlo]     = em0;
                g_em[(size_t)(b*64 + it)*NN + jlo + 8] = em1;
            }
        }
        __syncthreads();   // K stage reads complete

        if (st + 2 < NST) {
            const uint32_t dH = sb + ST_K + (st & 1)*36864, dL = dH + 18432;
            const int i0n = (st + 2) * 128;
            #pragma unroll
            for (int p = 0; p < 4; p++) {
                int idx = t + p*256; int row = idx >> 3, seg = idx & 7;
                cp16(dH + row*BPITCH + seg*16, &g_kh[(size_t)(b*NN + i0n + row)*CC + seg*8]);
                cp16(dL + row*BPITCH + seg*16, &g_kl[(size_t)(b*NN + i0n + row)*CC + seg*8]);
            }
            CP_COMMIT();
        }
    }

    if (qc == 0) {
        szi[w*16 + qr]     = 1.f / zacc0;
        szi[w*16 + qr + 8] = 1.f / zacc1;
    }
    __syncthreads();

    // az epilogue: az[t][j0+jl] = em[t][j0+jl] * zi[jl]  (g_em is L2-hot)
    const int jl = t & 127, tg = t >> 7;
    const float zil = szi[jl];
    #pragma unroll 4
    for (int tt = tg; tt < 64; tt += 2) {
        const size_t o = (size_t)(b*64 + tt)*NN + j0 + jl;
        g_azh[o] = __float2half_rn(g_em[o] * zil);
    }
}

// ------------------------------------------------------------------
// Kernel 3: apply + fused output projection.
// O[i,c] = sum_j (P~[j,i]*az[j,t]) * v[j,c]; then out = Wo@O + bo + O
// grid (NN/128, BB), 256 thr. Stage = 128 j-rows.
// smem: P 2x34816 @0, V 2x18432 @69632, az 2x512 @106496
// Epilogue reuses: res tile [c][n] pitch RPITCH @0, Wo ws @34816
// ------------------------------------------------------------------
#define AP_VB   69632
#define AP_AZB  106496
#define AP_SMEM 107520

__global__ void __launch_bounds__(256) apply_kernel(const float* __restrict__ Wo,
                                                    const float* __restrict__ bo,
                                                    float* __restrict__ out)
{
    extern __shared__ char smc[];
    const uint32_t sb = smem_to_u32(smc);
    const int b = blockIdx.y, i0 = blockIdx.x * 128;
    const int t = threadIdx.x, w = t >> 5, lane = t & 31;
    const int lr = lane & 7, g = lane >> 3, qr = lane >> 2, qc = lane & 3;
    const int t0 = blockIdx.x * 2;   // stats tile index of first 64-i half

    // prologue: j-stages 0, 1 (128 rows each)
    #pragma unroll
    for (int pf = 0; pf < 2; pf++) {
        const uint32_t pb = sb + pf*34816;
        const uint32_t vb = sb + AP_VB + pf*18432;
        const uint32_t ab = sb + AP_AZB + pf*512;
        const int j0 = pf * 128;
        #pragma unroll
        for (int p = 0; p < 8; p++) {
            int idx = t + p*256; int row = idx >> 4, seg = idx & 15;
            cp16(pb + row*APITCH + seg*16, &g_pf16[((size_t)b*NN + j0 + row)*NN + i0 + seg*8]);
        }
        #pragma unroll
        for (int p = 0; p < 4; p++) {
            int idx = t + p*256; int row = idx >> 3, seg = idx & 7;
            cp16(vb + row*BPITCH + seg*16, &g_vf[(size_t)(b*NN + j0 + row)*CC + seg*8]);
        }
        if (t < 32)
            cp16(ab + t*16, &g_azh[(size_t)(b*64 + t0 + (t >> 4))*NN + j0 + (t & 15)*8]);
        CP_COMMIT();
    }

    float O[8][4];
    #pragma unroll
    for (int cn = 0; cn < 8; cn++)
        #pragma unroll
        for (int u = 0; u < 4; u++) O[cn][u] = 0.f;

    for (int jt = 0; jt < NN/128; jt++) {
        if (jt < NN/128 - 1) CP_WAIT1(); else CP_WAIT0();
        __syncthreads();

        const uint32_t pb = sb + (jt & 1)*34816;
        const uint32_t vb = sb + AP_VB + (jt & 1)*18432;
        const char* azp = smc + AP_AZB + (jt & 1)*512 + (w >> 2)*256;

        // A = P~^T frags (m=i', k=j 0..127), scaled by az
        uint32_t A[8][4];
        #pragma unroll
        for (int ks = 0; ks < 8; ks++) {
            ldsm4t(addrAt(pb, w*16, ks*16, lr, g), A[ks]);
            uint32_t az01 = *(const uint32_t*)(azp + (ks*16 + 2*qc)*2);
            uint32_t az89 = *(const uint32_t*)(azp + (ks*16 + 2*qc + 8)*2);
            A[ks][0] = hmul2u(A[ks][0], az01);
            A[ks][1] = hmul2u(A[ks][1], az01);
            A[ks][2] = hmul2u(A[ks][2], az89);
            A[ks][3] = hmul2u(A[ks][3], az89);
        }
        #pragma unroll
        for (int cn = 0; cn < 8; cn++) {
            uint32_t vv[16];
            ldsm4t(addrBt(vb,  0, cn*8, lr, g), vv);
            ldsm4t(addrBt(vb, 32, cn*8, lr, g), vv + 4);
            ldsm4t(addrBt(vb, 64, cn*8, lr, g), vv + 8);
            ldsm4t(addrBt(vb, 96, cn*8, lr, g), vv + 12);
            #pragma unroll
            for (int ks = 0; ks < 8; ks++) mma16816h(O[cn], A[ks], vv[2*ks], vv[2*ks+1]);
        }
        __syncthreads();

        if (jt + 2 < NN/128) {
            const uint32_t dpb = sb + (jt & 1)*34816;
            const uint32_t dvb = sb + AP_VB + (jt & 1)*18432;
            const uint32_t dab = sb + AP_AZB + (jt & 1)*512;
            const int j0n = (jt + 2) * 128;
            #pragma unroll
            for (int p = 0; p < 8; p++) {
                int idx = t + p*256; int row = idx >> 4, seg = idx & 15;
                cp16(dpb + row*APITCH + seg*16, &g_pf16[((size_t)b*NN + j0n + row)*NN + i0 + seg*8]);
            }
            #pragma unroll
            for (int p = 0; p < 4; p++) {
                int idx = t + p*256; int row = idx >> 3, seg = idx & 7;
                cp16(dvb + row*BPITCH + seg*16, &g_vf[(size_t)(b*NN + j0n + row)*CC + seg*8]);
            }
            if (t < 32)
                cp16(dab + t*16, &g_azh[(size_t)(b*64 + t0 + (t >> 4))*NN + j0n + (t & 15)*8]);
            CP_COMMIT();
        }
    }

    // ---------- fused output projection ----------
    // res tile [c][n_local] pitch RPITCH floats @smc+0; Wo ws [cin][cout] @smc+34816
    float* rstile = reinterpret_cast<float*>(smc);
    float* wst    = reinterpret_cast<float*>(smc + 34816);

    {   // un-permute i' -> i, store O to smem transposed
        const int ia0 = swapbits(w*16 + qr);
        const int ia1 = swapbits(w*16 + qr + 8);
        #pragma unroll
        for (int cn = 0; cn < 8; cn++) {
            const int col = cn*8 + qc*2;
            rstile[(col    )*RPITCH + ia0] = O[cn][0];
            rstile[(col + 1)*RPITCH + ia0] = O[cn][1];
            rstile[(col    )*RPITCH + ia1] = O[cn][2];
            rstile[(col + 1)*RPITCH + ia1] = O[cn][3];
        }
    }
    for (int idx = t; idx < CC*CC; idx += 256) {
        int cout = idx >> 6, cin = idx & 63;
        wst[cin*PITCH + cout] = Wo[idx];
    }
    __syncthreads();

    const int tx = t & 15, ty = t >> 4;
    #pragma unroll
    for (int h = 0; h < 2; h++) {
        float acc[4][4];
        #pragma unroll
        for (int k = 0; k < 4; k++)
            #pragma unroll
            for (int j = 0; j < 4; j++) acc[k][j] = 0.f;

        #pragma unroll 4
        for (int ci = 0; ci < CC; ci++) {
            const float4 r4 = LD4(&rstile[ci*RPITCH + h*64 + 4*tx]);
            float wv[4];
            #pragma unroll
            for (int k = 0; k < 4; k++) wv[k] = wst[ci*PITCH + ty + 16*k];
            #pragma unroll
            for (int k = 0; k < 4; k++) {
                acc[k][0] = fmaf(wv[k], r4.x, acc[k][0]);
                acc[k][1] = fmaf(wv[k], r4.y, acc[k][1]);
                acc[k][2] = fmaf(wv[k], r4.z, acc[k][2]);
                acc[k][3] = fmaf(wv[k], r4.w, acc[k][3]);
            }
        }

        #pragma unroll
        for (int k = 0; k < 4; k++) {
            const int c = ty + 16*k;
            const float bvv = bo[c];
            const float4 resid = LD4(&rstile[c*RPITCH + h*64 + 4*tx]);
            float4 o;
            o.x = acc[k][0] + bvv + resid.x;
            o.y = acc[k][1] + bvv + resid.y;
            o.z = acc[k][2] + bvv + resid.z;
            o.w = acc[k][3] + bvv + resid.w;
            *(float4*)&out[(size_t)(b*CC + c)*NN + i0 + h*64 + 4*tx] = o;
        }
    }
}

// ------------------------------------------------------------------
extern "C" void kernel_launch(void* const* d_in, const int* in_sizes, int n_in,
                              void* d_out, int out_size)
{
    const float* x  = (const float*)d_in[0];
    const float* Wq = (const float*)d_in[1];
    const float* bq = (const float*)d_in[2];
    const float* Wk = (const float*)d_in[3];
    const float* bk = (const float*)d_in[4];
    const float* Wv = (const float*)d_in[5];
    const float* bv = (const float*)d_in[6];
    const float* Wo = (const float*)d_in[7];
    const float* bo = (const float*)d_in[8];
    float* out = (float*)d_out;

    const int QKV_SMEM = (3*CC*PITCH + CC*64) * 4;
    cudaFuncSetAttribute(qkv_kernel,   cudaFuncAttributeMaxDynamicSharedMemorySize, QKV_SMEM);
    cudaFuncSetAttribute(stats_kernel, cudaFuncAttributeMaxDynamicSharedMemorySize, ST_SMEM);
    cudaFuncSetAttribute(apply_kernel, cudaFuncAttributeMaxDynamicSharedMemorySize, AP_SMEM);

    qkv_kernel<<<dim3(NN/64, BB), 256, QKV_SMEM>>>(x, Wq, bq, Wk, bk, Wv, bv);
    stats_kernel<<<dim3(NN/128, BB), 256, ST_SMEM>>>();
    apply_kernel<<<dim3(NN/128, BB), 256, AP_SMEM>>>(Wo, bo, out);
}

// round 13
// speedup vs baseline: 1.1476x; 1.1476x over previous
#include <cuda_runtime.h>
#include <cuda_bf16.h>
#include <cuda_fp16.h>
#include <cstdint>

#define BB 8
#define CC 64
#define NN 4096
#define PITCH 68      // fp32 smem pitch (qkv ws / apply ws)
#define RPITCH 132    // fp32 pitch for apply res tile (128 n + pad)
#define BPITCH 144    // bf16/fp16 tile pitch bytes (64 elems + pad)
#define APITCH 272    // apply P-tile pitch bytes (128 fp16 + pad)

// ---------------- scratch ----------------
__device__ __nv_bfloat16 g_qh[BB*NN*CC], g_ql[BB*NN*CC];
__device__ __nv_bfloat16 g_kh[BB*NN*CC], g_kl[BB*NN*CC];
__device__ __half g_vf[BB*NN*CC];                   // V fp16 [b][j][c]
__device__ __half g_pf16[(size_t)BB*NN*NN];         // P~ fp16 [b][j][i-permuted]
__device__ __half g_azh[(size_t)BB*64*NN];          // az = e^{m_t}/Z_j fp16 [b][t][j]

#define LD4(p) (*(const float4*)(p))

__device__ __forceinline__ uint32_t smem_to_u32(const void* p) {
    uint32_t a;
    asm("{ .reg .u64 t; cvta.to.shared.u64 t, %1; cvt.u32.u64 %0, t; }" : "=r"(a) : "l"(p));
    return a;
}
__device__ __forceinline__ void ldsm4(uint32_t addr, uint32_t* r) {
    asm volatile("ldmatrix.sync.aligned.m8n8.x4.shared.b16 {%0,%1,%2,%3}, [%4];"
                 : "=r"(r[0]), "=r"(r[1]), "=r"(r[2]), "=r"(r[3]) : "r"(addr));
}
__device__ __forceinline__ void ldsm4t(uint32_t addr, uint32_t* r) {
    asm volatile("ldmatrix.sync.aligned.m8n8.x4.trans.shared.b16 {%0,%1,%2,%3}, [%4];"
                 : "=r"(r[0]), "=r"(r[1]), "=r"(r[2]), "=r"(r[3]) : "r"(addr));
}
__device__ __forceinline__ void mma16816(float* c, const uint32_t* a, uint32_t b0, uint32_t b1) {
    asm volatile("mma.sync.aligned.m16n8k16.row.col.f32.bf16.bf16.f32 "
                 "{%0,%1,%2,%3}, {%4,%5,%6,%7}, {%8,%9}, {%0,%1,%2,%3};"
                 : "+f"(c[0]), "+f"(c[1]), "+f"(c[2]), "+f"(c[3])
                 : "r"(a[0]), "r"(a[1]), "r"(a[2]), "r"(a[3]), "r"(b0), "r"(b1));
}
__device__ __forceinline__ void mma16816h(float* c, const uint32_t* a, uint32_t b0, uint32_t b1) {
    asm volatile("mma.sync.aligned.m16n8k16.row.col.f32.f16.f16.f32 "
                 "{%0,%1,%2,%3}, {%4,%5,%6,%7}, {%8,%9}, {%0,%1,%2,%3};"
                 : "+f"(c[0]), "+f"(c[1]), "+f"(c[2]), "+f"(c[3])
                 : "r"(a[0]), "r"(a[1]), "r"(a[2]), "r"(a[3]), "r"(b0), "r"(b1));
}
__device__ __forceinline__ uint32_t packh2(float lo, float hi) {
    __half2 h = __floats2half2_rn(lo, hi);
    return *reinterpret_cast<uint32_t*>(&h);
}
__device__ __forceinline__ uint32_t hmul2u(uint32_t a, uint32_t b) {
    __half2 r = __hmul2(*reinterpret_cast<__half2*>(&a), *reinterpret_cast<__half2*>(&b));
    return *reinterpret_cast<uint32_t*>(&r);
}
__device__ __forceinline__ void split2(float p0, float p1, uint32_t& h, uint32_t& l) {
    __nv_bfloat16 h0 = __float2bfloat16_rn(p0), h1 = __float2bfloat16_rn(p1);
    __nv_bfloat16 l0 = __float2bfloat16_rn(p0 - __bfloat162float(h0));
    __nv_bfloat16 l1 = __float2bfloat16_rn(p1 - __bfloat162float(h1));
    h = ((uint32_t)__bfloat16_as_ushort(h1) << 16) | __bfloat16_as_ushort(h0);
    l = ((uint32_t)__bfloat16_as_ushort(l1) << 16) | __bfloat16_as_ushort(l0);
}
__device__ __forceinline__ void cp16(uint32_t saddr, const void* gaddr) {
    asm volatile("cp.async.cg.shared.global [%0], [%1], 16;" :: "r"(saddr), "l"(gaddr));
}
#define CP_COMMIT() asm volatile("cp.async.commit_group;" ::: "memory")
#define CP_WAIT0()  asm volatile("cp.async.wait_group 0;" ::: "memory")
#define CP_WAIT1()  asm volatile("cp.async.wait_group 1;" ::: "memory")

// A fragment m16k16 from [m][k] storage (pitch BPITCH)
__device__ __forceinline__ uint32_t addrA(uint32_t base, int r0, int c0, int lr, int g) {
    return base + (uint32_t)(r0 + lr + ((g & 1) << 3)) * BPITCH + ((uint32_t)(c0 + ((g >> 1) << 3)) << 1);
}
// B fragments from [n][k] storage
__device__ __forceinline__ uint32_t addrB(uint32_t base, int n0, int k0, int lr, int g) {
    return base + (uint32_t)(n0 + lr) * BPITCH + ((uint32_t)(k0 + g * 8) << 1);
}
// A fragment m16k16 via trans from [k][m] storage (pitch APITCH)
__device__ __forceinline__ uint32_t addrAt(uint32_t base, int m0, int k0, int lr, int g) {
    return base + (uint32_t)(k0 + ((g >> 1) << 3) + lr) * APITCH + ((uint32_t)(m0 + ((g & 1) << 3)) << 1);
}
// B fragments via trans from [k][n] storage (pitch BPITCH)
__device__ __forceinline__ uint32_t addrBt(uint32_t base, int k0, int n0, int lr, int g) {
    return base + (uint32_t)(k0 + g * 8 + lr) * BPITCH + ((uint32_t)n0 << 1);
}
// permutation: swap bits [4:3] <-> [2:1] (i within 64-tile; bit 6 preserved)
__device__ __forceinline__ int swapbits(int idx) {
    return (idx & 0x61) | ((idx & 0x18) >> 2) | ((idx & 0x06) << 2);
}

// ------------------------------------------------------------------
// Kernel 1: q,k -> bf16 hi/lo planes [b][n][c]; v -> fp16 [b][n][c]
// ------------------------------------------------------------------
__global__ void qkv_kernel(const float* __restrict__ x,
                           const float* __restrict__ Wq, const float* __restrict__ bq,
                           const float* __restrict__ Wk, const float* __restrict__ bk,
                           const float* __restrict__ Wv, const float* __restrict__ bv)
{
    extern __shared__ float smf[];
    float* ws = smf;
    float* xs = smf + 3*CC*PITCH;
    const int b  = blockIdx.y;
    const int n0 = blockIdx.x * 64;
    const int t  = threadIdx.x;

    const float* Wmats[3] = {Wq, Wk, Wv};
    #pragma unroll
    for (int m = 0; m < 3; m++)
        for (int idx = t; idx < CC*CC; idx += 256) {
            int cout = idx >> 6, cin = idx & 63;
            ws[(m*CC + cin)*PITCH + cout] = Wmats[m][idx];
        }
    for (int idx = t; idx < CC*64; idx += 256) {
        int cin = idx >> 6, n = idx & 63;
        xs[cin*64 + n] = x[(size_t)(b*CC + cin)*NN + n0 + n];
    }
    __syncthreads();

    const int tx = t & 15, ty = t >> 4;
    float acc[3][4][4];
    #pragma unroll
    for (int m = 0; m < 3; m++)
        #pragma unroll
        for (int k = 0; k < 4; k++)
            #pragma unroll
            for (int j = 0; j < 4; j++) acc[m][k][j] = 0.f;

    #pragma unroll 4
    for (int ci = 0; ci < CC; ci++) {
        float xv[4];
        #pragma unroll
        for (int k = 0; k < 4; k++) xv[k] = xs[ci*64 + ty + 16*k];
        #pragma unroll
        for (int m = 0; m < 3; m++) {
            const float4 w4 = LD4(&ws[(m*CC + ci)*PITCH + 4*tx]);
            #pragma unroll
            for (int k = 0; k < 4; k++) {
                acc[m][k][0] = fmaf(xv[k], w4.x, acc[m][k][0]);
                acc[m][k][1] = fmaf(xv[k], w4.y, acc[m][k][1]);
                acc[m][k][2] = fmaf(xv[k], w4.z, acc[m][k][2]);
                acc[m][k][3] = fmaf(xv[k], w4.w, acc[m][k][3]);
            }
        }
    }

    const float* biases[2] = {bq, bk};
    __nv_bfloat16* outsH[2] = {g_qh, g_kh};
    __nv_bfloat16* outsL[2] = {g_ql, g_kl};
    #pragma unroll
    for (int m = 0; m < 2; m++) {
        const float4 bb4 = LD4(&biases[m][4*tx]);
        const float bbv[4] = {bb4.x, bb4.y, bb4.z, bb4.w};
        #pragma unroll
        for (int k = 0; k < 4; k++) {
            int n = n0 + ty + 16*k;
            uint32_t Hp[2], Lp[2];
            #pragma unroll
            for (int jp = 0; jp < 2; jp++) {
                float v0 = acc[m][k][2*jp]   + bbv[2*jp];
                float v1 = acc[m][k][2*jp+1] + bbv[2*jp+1];
                split2(v0, v1, Hp[jp], Lp[jp]);
            }
            size_t idx = (size_t)(b*NN + n)*CC + 4*tx;
            *reinterpret_cast<uint2*>(&outsH[m][idx]) = make_uint2(Hp[0], Hp[1]);
            *reinterpret_cast<uint2*>(&outsL[m][idx]) = make_uint2(Lp[0], Lp[1]);
        }
    }
    {
        const float4 bb4 = LD4(&bv[4*tx]);
        #pragma unroll
        for (int k = 0; k < 4; k++) {
            int n = n0 + ty + 16*k;
            uint32_t u0 = packh2(acc[2][k][0] + bb4.x, acc[2][k][1] + bb4.y);
            uint32_t u1 = packh2(acc[2][k][2] + bb4.z, acc[2][k][3] + bb4.w);
            *reinterpret_cast<uint2*>(&g_vf[(size_t)(b*NN + n)*CC + 4*tx]) = make_uint2(u0, u1);
        }
    }
}

// ------------------------------------------------------------------
// Kernel 2 (R10 version): stats, K ping-pong of 64-i tiles; em in smem;
// az fused epilogue.
// grid (NN/128, BB), 256 thr.
// smem: Q 2x18432 @0, K ping-pong 2x18432 @36864, em 64x128 f32 @73728, zi @106496
// ------------------------------------------------------------------
#define ST_K    36864
#define ST_EM   73728
#define ST_ZI   106496
#define ST_SMEM 107008

__global__ void __launch_bounds__(256) stats_kernel()
{
    extern __shared__ char smc[];
    const uint32_t sb = smem_to_u32(smc);
    float* sem = reinterpret_cast<float*>(smc + ST_EM);
    float* szi = reinterpret_cast<float*>(smc + ST_ZI);
    const int b = blockIdx.y, j0 = blockIdx.x * 128;
    const int t = threadIdx.x, w = t >> 5, lane = t & 31;
    const int lr = lane & 7, g = lane >> 3, qr = lane >> 2, qc = lane & 3;

    // prefetch K tiles 0,1
    #pragma unroll
    for (int pf = 0; pf < 2; pf++) {
        const uint32_t dH = sb + ST_K + pf*18432, dL = dH + 9216;
        const int i0n = pf * 64;
        #pragma unroll
        for (int p = 0; p < 2; p++) {
            int idx = t + p*256; int row = idx >> 3, seg = idx & 7;
            cp16(dH + row*BPITCH + seg*16, &g_kh[(size_t)(b*NN + i0n + row)*CC + seg*8]);
            cp16(dL + row*BPITCH + seg*16, &g_kl[(size_t)(b*NN + i0n + row)*CC + seg*8]);
        }
        CP_COMMIT();
    }

    {   // Q tiles (128 rows, plain loads)
        const __nv_bfloat16* sH = &g_qh[(size_t)(b*NN + j0)*CC];
        const __nv_bfloat16* sL = &g_ql[(size_t)(b*NN + j0)*CC];
        for (int idx = t; idx < 1024; idx += 256) {
            int row = idx >> 3, seg = idx & 7;
            *(uint4*)(smc + row*BPITCH + seg*16)         = *(const uint4*)&sH[row*64 + seg*8];
            *(uint4*)(smc + 18432 + row*BPITCH + seg*16) = *(const uint4*)&sL[row*64 + seg*8];
        }
    }
    __syncthreads();

    uint32_t Ah[4][4], Al[4][4];
    #pragma unroll
    for (int ks = 0; ks < 4; ks++) {
        ldsm4(addrA(sb,         w*16, ks*16, lr, g), Ah[ks]);
        ldsm4(addrA(sb + 18432, w*16, ks*16, lr, g), Al[ks]);
    }

    float zacc0 = 0.f, zacc1 = 0.f;
    const int jlo = j0 + w*16 + qr;

    for (int it = 0; it < NN/64; it++) {
        if (it < NN/64 - 1) CP_WAIT1(); else CP_WAIT0();
        __syncthreads();

        const uint32_t kbH = sb + ST_K + (it & 1)*18432, kbL = kbH + 9216;
        float C[8][4];
        #pragma unroll
        for (int nt = 0; nt < 8; nt++) {
            uint32_t bh[8], bl[8];
            ldsm4(addrB(kbH, nt*8,  0, lr, g), bh);
            ldsm4(addrB(kbH, nt*8, 32, lr, g), bh + 4);
            ldsm4(addrB(kbL, nt*8,  0, lr, g), bl);
            ldsm4(addrB(kbL, nt*8, 32, lr, g), bl + 4);
            C[nt][0] = C[nt][1] = C[nt][2] = C[nt][3] = 0.f;
            #pragma unroll
            for (int ks = 0; ks < 4; ks++) mma16816(C[nt], Ah[ks], bh[2*ks], bh[2*ks+1]);
            #pragma unroll
            for (int ks = 0; ks < 4; ks++) mma16816(C[nt], Ah[ks], bl[2*ks], bl[2*ks+1]);
            #pragma unroll
            for (int ks = 0; ks < 4; ks++) mma16816(C[nt], Al[ks], bh[2*ks], bh[2*ks+1]);
        }

        float pm0 = C[0][0], pm1 = C[0][2];
        #pragma unroll
        for (int nt = 0; nt < 8; nt++) {
            pm0 = fmaxf(pm0, fmaxf(C[nt][0], C[nt][1]));
            pm1 = fmaxf(pm1, fmaxf(C[nt][2], C[nt][3]));
        }
        pm0 = fmaxf(pm0, __shfl_xor_sync(0xffffffffu, pm0, 1));
        pm0 = fmaxf(pm0, __shfl_xor_sync(0xffffffffu, pm0, 2));
        pm1 = fmaxf(pm1, __shfl_xor_sync(0xffffffffu, pm1, 1));
        pm1 = fmaxf(pm1, __shfl_xor_sync(0xffffffffu, pm1, 2));
        const float em0 = __expf(pm0), em1 = __expf(pm1);

        float ps0 = 0.f, ps1 = 0.f;
        #pragma unroll
        for (int nt = 0; nt < 8; nt++) {
            C[nt][0] = __expf(C[nt][0] - pm0);
            C[nt][1] = __expf(C[nt][1] - pm0);
            C[nt][2] = __expf(C[nt][2] - pm1);
            C[nt][3] = __expf(C[nt][3] - pm1);
            ps0 += C[nt][0] + C[nt][1];
            ps1 += C[nt][2] + C[nt][3];
        }
        ps0 += __shfl_xor_sync(0xffffffffu, ps0, 1);
        ps0 += __shfl_xor_sync(0xffffffffu, ps0, 2);
        ps1 += __shfl_xor_sync(0xffffffffu, ps1, 1);
        ps1 += __shfl_xor_sync(0xffffffffu, ps1, 2);
        zacc0 += em0 * ps0;
        zacc1 += em1 * ps1;

        // coalesced permuted store
        const size_t rb0 = (size_t)(b*NN + jlo)*NN + it*64;
        const size_t rb1 = rb0 + (size_t)8*NN;
        #pragma unroll
        for (int pk = 0; pk < 2; pk++) {
            uint4 u0, u1;
            u0.x = packh2(C[pk*4+0][0], C[pk*4+0][1]);
            u0.y = packh2(C[pk*4+1][0], C[pk*4+1][1]);
            u0.z = packh2(C[pk*4+2][0], C[pk*4+2][1]);
            u0.w = packh2(C[pk*4+3][0], C[pk*4+3][1]);
            u1.x = packh2(C[pk*4+0][2], C[pk*4+0][3]);
            u1.y = packh2(C[pk*4+1][2], C[pk*4+1][3]);
            u1.z = packh2(C[pk*4+2][2], C[pk*4+2][3]);
            u1.w = packh2(C[pk*4+3][2], C[pk*4+3][3]);
            *(uint4*)&g_pf16[rb0 + pk*32 + qc*8] = u0;
            *(uint4*)&g_pf16[rb1 + pk*32 + qc*8] = u1;
        }
        if (qc == 0) {
            sem[it*128 + w*16 + qr]     = em0;
            sem[it*128 + w*16 + qr + 8] = em1;
        }
        __syncthreads();

        if (it + 2 < NN/64) {
            const uint32_t dH = sb + ST_K + (it & 1)*18432, dL = dH + 9216;
            const int i0n = (it + 2) * 64;
            #pragma unroll
            for (int p = 0; p < 2; p++) {
                int idx = t + p*256; int row = idx >> 3, seg = idx & 7;
                cp16(dH + row*BPITCH + seg*16, &g_kh[(size_t)(b*NN + i0n + row)*CC + seg*8]);
                cp16(dL + row*BPITCH + seg*16, &g_kl[(size_t)(b*NN + i0n + row)*CC + seg*8]);
            }
            CP_COMMIT();
        }
    }

    if (qc == 0) {
        szi[w*16 + qr]     = 1.f / zacc0;
        szi[w*16 + qr + 8] = 1.f / zacc1;
    }
    __syncthreads();

    // az epilogue from smem: az[t][j0+jl] = em[t][jl] * zi[jl]
    const int jl = t & 127, tg = t >> 7;
    const float zil = szi[jl];
    #pragma unroll 4
    for (int tt = tg; tt < 64; tt += 2)
        g_azh[(size_t)(b*64 + tt)*NN + j0 + jl] = __float2half_rn(sem[tt*128 + jl] * zil);
}

// ------------------------------------------------------------------
// Kernel 3: apply (R10 loop) + fused output projection (R12 epilogue).
// grid (NN/128, BB), 256 thr. Stage = 128 j-rows.
// smem: P 2x34816 @0, V 2x18432 @69632, az 2x512 @106496
// Epilogue reuse: res tile [c][n] pitch RPITCH @0, Wo ws @34816
// ------------------------------------------------------------------
#define AP_VB   69632
#define AP_AZB  106496
#define AP_SMEM 107520

__global__ void __launch_bounds__(256) apply_kernel(const float* __restrict__ Wo,
                                                    const float* __restrict__ bo,
                                                    float* __restrict__ out)
{
    extern __shared__ char smc[];
    const uint32_t sb = smem_to_u32(smc);
    const int b = blockIdx.y, i0 = blockIdx.x * 128;
    const int t = threadIdx.x, w = t >> 5, lane = t & 31;
    const int lr = lane & 7, g = lane >> 3, qr = lane >> 2, qc = lane & 3;
    const int t0 = blockIdx.x * 2;   // stats tile index of first 64-i half

    // prologue: j-stages 0, 1 (128 rows each)
    #pragma unroll
    for (int pf = 0; pf < 2; pf++) {
        const uint32_t pb = sb + pf*34816;
        const uint32_t vb = sb + AP_VB + pf*18432;
        const uint32_t ab = sb + AP_AZB + pf*512;
        const int j0 = pf * 128;
        #pragma unroll
        for (int p = 0; p < 8; p++) {
            int idx = t + p*256; int row = idx >> 4, seg = idx & 15;
            cp16(pb + row*APITCH + seg*16, &g_pf16[((size_t)b*NN + j0 + row)*NN + i0 + seg*8]);
        }
        #pragma unroll
        for (int p = 0; p < 4; p++) {
            int idx = t + p*256; int row = idx >> 3, seg = idx & 7;
            cp16(vb + row*BPITCH + seg*16, &g_vf[(size_t)(b*NN + j0 + row)*CC + seg*8]);
        }
        if (t < 32)
            cp16(ab + t*16, &g_azh[(size_t)(b*64 + t0 + (t >> 4))*NN + j0 + (t & 15)*8]);
        CP_COMMIT();
    }

    float O[8][4];
    #pragma unroll
    for (int cn = 0; cn < 8; cn++)
        #pragma unroll
        for (int u = 0; u < 4; u++) O[cn][u] = 0.f;

    for (int jt = 0; jt < NN/128; jt++) {
        if (jt < NN/128 - 1) CP_WAIT1(); else CP_WAIT0();
        __syncthreads();

        const uint32_t pb = sb + (jt & 1)*34816;
        const uint32_t vb = sb + AP_VB + (jt & 1)*18432;
        const char* azp = smc + AP_AZB + (jt & 1)*512 + (w >> 2)*256;

        // A = P~^T frags (m=i', k=j 0..127), scaled by az
        uint32_t A[8][4];
        #pragma unroll
        for (int ks = 0; ks < 8; ks++) {
            ldsm4t(addrAt(pb, w*16, ks*16, lr, g), A[ks]);
            uint32_t az01 = *(const uint32_t*)(azp + (ks*16 + 2*qc)*2);
            uint32_t az89 = *(const uint32_t*)(azp + (ks*16 + 2*qc + 8)*2);
            A[ks][0] = hmul2u(A[ks][0], az01);
            A[ks][1] = hmul2u(A[ks][1], az01);
            A[ks][2] = hmul2u(A[ks][2], az89);
            A[ks][3] = hmul2u(A[ks][3], az89);
        }
        #pragma unroll
        for (int cn = 0; cn < 8; cn++) {
            uint32_t vv[16];
            ldsm4t(addrBt(vb,  0, cn*8, lr, g), vv);
            ldsm4t(addrBt(vb, 32, cn*8, lr, g), vv + 4);
            ldsm4t(addrBt(vb, 64, cn*8, lr, g), vv + 8);
            ldsm4t(addrBt(vb, 96, cn*8, lr, g), vv + 12);
            #pragma unroll
            for (int ks = 0; ks < 8; ks++) mma16816h(O[cn], A[ks], vv[2*ks], vv[2*ks+1]);
        }
        __syncthreads();

        if (jt + 2 < NN/128) {
            const uint32_t dpb = sb + (jt & 1)*34816;
            const uint32_t dvb = sb + AP_VB + (jt & 1)*18432;
            const uint32_t dab = sb + AP_AZB + (jt & 1)*512;
            const int j0n = (jt + 2) * 128;
            #pragma unroll
            for (int p = 0; p < 8; p++) {
                int idx = t + p*256; int row = idx >> 4, seg = idx & 15;
                cp16(dpb + row*APITCH + seg*16, &g_pf16[((size_t)b*NN + j0n + row)*NN + i0 + seg*8]);
            }
            #pragma unroll
            for (int p = 0; p < 4; p++) {
                int idx = t + p*256; int row = idx >> 3, seg = idx & 7;
                cp16(dvb + row*BPITCH + seg*16, &g_vf[(size_t)(b*NN + j0n + row)*CC + seg*8]);
            }
            if (t < 32)
                cp16(dab + t*16, &g_azh[(size_t)(b*64 + t0 + (t >> 4))*NN + j0n + (t & 15)*8]);
            CP_COMMIT();
        }
    }

    // ---------- fused output projection ----------
    float* rstile = reinterpret_cast<float*>(smc);            // [c][n_local] pitch RPITCH
    float* wst    = reinterpret_cast<float*>(smc + 34816);    // [cin][cout] pitch PITCH

    {   // un-permute i' -> i, store O to smem transposed
        const int ia0 = swapbits(w*16 + qr);
        const int ia1 = swapbits(w*16 + qr + 8);
        #pragma unroll
        for (int cn = 0; cn < 8; cn++) {
            const int col = cn*8 + qc*2;
            rstile[(col    )*RPITCH + ia0] = O[cn][0];
            rstile[(col + 1)*RPITCH + ia0] = O[cn][1];
            rstile[(col    )*RPITCH + ia1] = O[cn][2];
            rstile[(col + 1)*RPITCH + ia1] = O[cn][3];
        }
    }
    for (int idx = t; idx < CC*CC; idx += 256) {
        int cout = idx >> 6, cin = idx & 63;
        wst[cin*PITCH + cout] = Wo[idx];
    }
    __syncthreads();

    const int tx = t & 15, ty = t >> 4;
    #pragma unroll
    for (int h = 0; h < 2; h++) {
        float acc[4][4];
        #pragma unroll
        for (int k = 0; k < 4; k++)
            #pragma unroll
            for (int j = 0; j < 4; j++) acc[k][j] = 0.f;

        #pragma unroll 4
        for (int ci = 0; ci < CC; ci++) {
            const float4 r4 = LD4(&rstile[ci*RPITCH + h*64 + 4*tx]);
            float wv[4];
            #pragma unroll
            for (int k = 0; k < 4; k++) wv[k] = wst[ci*PITCH + ty + 16*k];
            #pragma unroll
            for (int k = 0; k < 4; k++) {
                acc[k][0] = fmaf(wv[k], r4.x, acc[k][0]);
                acc[k][1] = fmaf(wv[k], r4.y, acc[k][1]);
                acc[k][2] = fmaf(wv[k], r4.z, acc[k][2]);
                acc[k][3] = fmaf(wv[k], r4.w, acc[k][3]);
            }
        }

        #pragma unroll
        for (int k = 0; k < 4; k++) {
            const int c = ty + 16*k;
            const float bvv = bo[c];
            const float4 resid = LD4(&rstile[c*RPITCH + h*64 + 4*tx]);
            float4 o;
            o.x = acc[k][0] + bvv + resid.x;
            o.y = acc[k][1] + bvv + resid.y;
            o.z = acc[k][2] + bvv + resid.z;
            o.w = acc[k][3] + bvv + resid.w;
            *(float4*)&out[(size_t)(b*CC + c)*NN + i0 + h*64 + 4*tx] = o;
        }
    }
}

// ------------------------------------------------------------------
extern "C" void kernel_launch(void* const* d_in, const int* in_sizes, int n_in,
                              void* d_out, int out_size)
{
    const float* x  = (const float*)d_in[0];
    const float* Wq = (const float*)d_in[1];
    const float* bq = (const float*)d_in[2];
    const float* Wk = (const float*)d_in[3];
    const float* bk = (const float*)d_in[4];
    const float* Wv = (const float*)d_in[5];
    const float* bv = (const float*)d_in[6];
    const float* Wo = (const float*)d_in[7];
    const float* bo = (const float*)d_in[8];
    float* out = (float*)d_out;

    const int QKV_SMEM = (3*CC*PITCH + CC*64) * 4;
    cudaFuncSetAttribute(qkv_kernel,   cudaFuncAttributeMaxDynamicSharedMemorySize, QKV_SMEM);
    cudaFuncSetAttribute(stats_kernel, cudaFuncAttributeMaxDynamicSharedMemorySize, ST_SMEM);
    cudaFuncSetAttribute(apply_kernel, cudaFuncAttributeMaxDynamicSharedMemorySize, AP_SMEM);

    qkv_kernel<<<dim3(NN/64, BB), 256, QKV_SMEM>>>(x, Wq, bq, Wk, bk, Wv, bv);
    stats_kernel<<<dim3(NN/128, BB), 256, ST_SMEM>>>();
    apply_kernel<<<dim3(NN/128, BB), 256, AP_SMEM>>>(Wo, bo, out);
}

// round 15
// speedup vs baseline: 1.1892x; 1.0363x over previous
#include <cuda_runtime.h>
#include <cuda_bf16.h>
#include <cuda_fp16.h>
#include <cstdint>

#define BB 8
#define CC 64
#define NN 4096
#define PITCH 68      // fp32 smem pitch (qkv ws / apply ws)
#define RPITCH 132    // fp32 pitch for apply res tile (128 n + pad)
#define BPITCH 144    // bf16/fp16 tile pitch bytes (64 elems + pad)
#define APITCH 272    // apply P-tile pitch bytes (128 fp16 + pad)

// ---------------- scratch ----------------
__device__ __nv_bfloat16 g_qh[BB*NN*CC], g_ql[BB*NN*CC];
__device__ __nv_bfloat16 g_kh[BB*NN*CC], g_kl[BB*NN*CC];
__device__ __half g_vf[BB*NN*CC];                   // V fp16 [b][j][c]
__device__ __half g_pf16[(size_t)BB*NN*NN];         // P~ fp16 [b][j][i-permuted]
__device__ __half g_azh[(size_t)BB*64*NN];          // az = e^{m_t}/Z_j fp16 [b][t][j]

#define LD4(p) (*(const float4*)(p))

__device__ __forceinline__ uint32_t smem_to_u32(const void* p) {
    uint32_t a;
    asm("{ .reg .u64 t; cvta.to.shared.u64 t, %1; cvt.u32.u64 %0, t; }" : "=r"(a) : "l"(p));
    return a;
}
__device__ __forceinline__ void ldsm4(uint32_t addr, uint32_t* r) {
    asm volatile("ldmatrix.sync.aligned.m8n8.x4.shared.b16 {%0,%1,%2,%3}, [%4];"
                 : "=r"(r[0]), "=r"(r[1]), "=r"(r[2]), "=r"(r[3]) : "r"(addr));
}
__device__ __forceinline__ void ldsm4t(uint32_t addr, uint32_t* r) {
    asm volatile("ldmatrix.sync.aligned.m8n8.x4.trans.shared.b16 {%0,%1,%2,%3}, [%4];"
                 : "=r"(r[0]), "=r"(r[1]), "=r"(r[2]), "=r"(r[3]) : "r"(addr));
}
__device__ __forceinline__ void mma16816(float* c, const uint32_t* a, uint32_t b0, uint32_t b1) {
    asm volatile("mma.sync.aligned.m16n8k16.row.col.f32.bf16.bf16.f32 "
                 "{%0,%1,%2,%3}, {%4,%5,%6,%7}, {%8,%9}, {%0,%1,%2,%3};"
                 : "+f"(c[0]), "+f"(c[1]), "+f"(c[2]), "+f"(c[3])
                 : "r"(a[0]), "r"(a[1]), "r"(a[2]), "r"(a[3]), "r"(b0), "r"(b1));
}
__device__ __forceinline__ void mma16816h(float* c, const uint32_t* a, uint32_t b0, uint32_t b1) {
    asm volatile("mma.sync.aligned.m16n8k16.row.col.f32.f16.f16.f32 "
                 "{%0,%1,%2,%3}, {%4,%5,%6,%7}, {%8,%9}, {%0,%1,%2,%3};"
                 : "+f"(c[0]), "+f"(c[1]), "+f"(c[2]), "+f"(c[3])
                 : "r"(a[0]), "r"(a[1]), "r"(a[2]), "r"(a[3]), "r"(b0), "r"(b1));
}
__device__ __forceinline__ uint32_t packh2(float lo, float hi) {
    __half2 h = __floats2half2_rn(lo, hi);
    return *reinterpret_cast<uint32_t*>(&h);
}
__device__ __forceinline__ uint32_t hmul2u(uint32_t a, uint32_t b) {
    __half2 r = __hmul2(*reinterpret_cast<__half2*>(&a), *reinterpret_cast<__half2*>(&b));
    return *reinterpret_cast<uint32_t*>(&r);
}
__device__ __forceinline__ void split2(float p0, float p1, uint32_t& h, uint32_t& l) {
    __nv_bfloat16 h0 = __float2bfloat16_rn(p0), h1 = __float2bfloat16_rn(p1);
    __nv_bfloat16 l0 = __float2bfloat16_rn(p0 - __bfloat162float(h0));
    __nv_bfloat16 l1 = __float2bfloat16_rn(p1 - __bfloat162float(h1));
    h = ((uint32_t)__bfloat16_as_ushort(h1) << 16) | __bfloat16_as_ushort(h0);
    l = ((uint32_t)__bfloat16_as_ushort(l1) << 16) | __bfloat16_as_ushort(l0);
}
__device__ __forceinline__ void cp16(uint32_t saddr, const void* gaddr) {
    asm volatile("cp.async.cg.shared.global [%0], [%1], 16;" :: "r"(saddr), "l"(gaddr));
}
#define CP_COMMIT() asm volatile("cp.async.commit_group;" ::: "memory")
#define CP_WAIT0()  asm volatile("cp.async.wait_group 0;" ::: "memory")
#define CP_WAIT1()  asm volatile("cp.async.wait_group 1;" ::: "memory")

// A fragment m16k16 from [m][k] storage (pitch BPITCH)
__device__ __forceinline__ uint32_t addrA(uint32_t base, int r0, int c0, int lr, int g) {
    return base + (uint32_t)(r0 + lr + ((g & 1) << 3)) * BPITCH + ((uint32_t)(c0 + ((g >> 1) << 3)) << 1);
}
// B fragments from [n][k] storage
__device__ __forceinline__ uint32_t addrB(uint32_t base, int n0, int k0, int lr, int g) {
    return base + (uint32_t)(n0 + lr) * BPITCH + ((uint32_t)(k0 + g * 8) << 1);
}
// A fragment m16k16 via trans from [k][m] storage (pitch APITCH)
__device__ __forceinline__ uint32_t addrAt(uint32_t base, int m0, int k0, int lr, int g) {
    return base + (uint32_t)(k0 + ((g >> 1) << 3) + lr) * APITCH + ((uint32_t)(m0 + ((g & 1) << 3)) << 1);
}
// B fragments via trans from [k][n] storage (pitch BPITCH)
__device__ __forceinline__ uint32_t addrBt(uint32_t base, int k0, int n0, int lr, int g) {
    return base + (uint32_t)(k0 + g * 8 + lr) * BPITCH + ((uint32_t)n0 << 1);
}
// permutation: swap bits [4:3] <-> [2:1] (i within 64-tile; bit 6 preserved)
__device__ __forceinline__ int swapbits(int idx) {
    return (idx & 0x61) | ((idx & 0x18) >> 2) | ((idx & 0x06) << 2);
}

// ------------------------------------------------------------------
// Kernel 1: q,k -> bf16 hi/lo planes [b][n][c]; v -> fp16 [b][n][c]
// grid (NN/256, BB), 256 thr. Weights loaded once, 4 x-tiles ping-pong.
// smem: ws 3x64x68 f32 @0 (52224 B), xs 2x(64x64 f32) @52224
// ------------------------------------------------------------------
#define QK_X     52224
#define QKV_SMEM 84992

__global__ void __launch_bounds__(256) qkv_kernel(const float* __restrict__ x,
                           const float* __restrict__ Wq, const float* __restrict__ bq,
                           const float* __restrict__ Wk, const float* __restrict__ bk,
                           const float* __restrict__ Wv, const float* __restrict__ bv)
{
    extern __shared__ char smc[];
    const uint32_t sb = smem_to_u32(smc);
    float* ws = reinterpret_cast<float*>(smc);
    const int b    = blockIdx.y;
    const int nb0  = blockIdx.x * 256;
    const int t    = threadIdx.x;

    // prefetch x tiles 0,1 (each: 64 cin rows x 64 n floats = 64 x 16 cp16)
    #pragma unroll
    for (int pf = 0; pf < 2; pf++) {
        const uint32_t dx = sb + QK_X + pf*16384;
        const int n0 = nb0 + pf*64;
        #pragma unroll
        for (int p = 0; p < 4; p++) {
            int idx = t + p*256; int cin = idx >> 4, seg = idx & 15;
            cp16(dx + cin*256 + seg*16, &x[(size_t)(b*CC + cin)*NN + n0 + seg*4]);
        }
        CP_COMMIT();
    }

    // weights (transposed) once
    const float* Wmats[3] = {Wq, Wk, Wv};
    #pragma unroll
    for (int m = 0; m < 3; m++)
        for (int idx = t; idx < CC*CC; idx += 256) {
            int cout = idx >> 6, cin = idx & 63;
            ws[(m*CC + cin)*PITCH + cout] = Wmats[m][idx];
        }

    const int tx = t & 15, ty = t >> 4;
    // biases hoisted
    const float4 bq4 = LD4(&bq[4*tx]);
    const float4 bk4 = LD4(&bk[4*tx]);
    const float4 bv4 = LD4(&bv[4*tx]);
    const float bQ[4] = {bq4.x, bq4.y, bq4.z, bq4.w};
    const float bK[4] = {bk4.x, bk4.y, bk4.z, bk4.w};

    for (int tt = 0; tt < 4; tt++) {
        if (tt < 3) CP_WAIT1(); else CP_WAIT0();
        __syncthreads();
        const float* xs = reinterpret_cast<const float*>(smc + QK_X + (tt & 1)*16384);
        const int n0 = nb0 + tt*64;

        float acc[3][4][4];
        #pragma unroll
        for (int m = 0; m < 3; m++)
            #pragma unroll
            for (int k = 0; k < 4; k++)
                #pragma unroll
                for (int j = 0; j < 4; j++) acc[m][k][j] = 0.f;

        #pragma unroll 4
        for (int ci = 0; ci < CC; ci++) {
            float xv[4];
            #pragma unroll
            for (int k = 0; k < 4; k++) xv[k] = xs[ci*64 + ty + 16*k];
            #pragma unroll
            for (int m = 0; m < 3; m++) {
                const float4 w4 = LD4(&ws[(m*CC + ci)*PITCH + 4*tx]);
                #pragma unroll
                for (int k = 0; k < 4; k++) {
                    acc[m][k][0] = fmaf(xv[k], w4.x, acc[m][k][0]);
                    acc[m][k][1] = fmaf(xv[k], w4.y, acc[m][k][1]);
                    acc[m][k][2] = fmaf(xv[k], w4.z, acc[m][k][2]);
                    acc[m][k][3] = fmaf(xv[k], w4.w, acc[m][k][3]);
                }
            }
        }
        __syncthreads();   // xs reads done before next prefetch overwrites

        if (tt + 2 < 4) {
            const uint32_t dx = sb + QK_X + (tt & 1)*16384;
            const int n0n = nb0 + (tt + 2)*64;
            #pragma unroll
            for (int p = 0; p < 4; p++) {
                int idx = t + p*256; int cin = idx >> 4, seg = idx & 15;
                cp16(dx + cin*256 + seg*16, &x[(size_t)(b*CC + cin)*NN + n0n + seg*4]);
            }
            CP_COMMIT();
        }

        // epilogue: q,k bf16 hi/lo; v fp16
        const float* bArr[2] = {bQ, bK};
        __nv_bfloat16* outsH[2] = {g_qh, g_kh};
        __nv_bfloat16* outsL[2] = {g_ql, g_kl};
        #pragma unroll
        for (int m = 0; m < 2; m++) {
            #pragma unroll
            for (int k = 0; k < 4; k++) {
                int n = n0 + ty + 16*k;
                uint32_t Hp[2], Lp[2];
                #pragma unroll
                for (int jp = 0; jp < 2; jp++) {
                    float v0 = acc[m][k][2*jp]   + bArr[m][2*jp];
                    float v1 = acc[m][k][2*jp+1] + bArr[m][2*jp+1];
                    split2(v0, v1, Hp[jp], Lp[jp]);
                }
                size_t idx = (size_t)(b*NN + n)*CC + 4*tx;
                *reinterpret_cast<uint2*>(&outsH[m][idx]) = make_uint2(Hp[0], Hp[1]);
                *reinterpret_cast<uint2*>(&outsL[m][idx]) = make_uint2(Lp[0], Lp[1]);
            }
        }
        #pragma unroll
        for (int k = 0; k < 4; k++) {
            int n = n0 + ty + 16*k;
            uint32_t u0 = packh2(acc[2][k][0] + bv4.x, acc[2][k][1] + bv4.y);
            uint32_t u1 = packh2(acc[2][k][2] + bv4.z, acc[2][k][3] + bv4.w);
            *reinterpret_cast<uint2*>(&g_vf[(size_t)(b*NN + n)*CC + 4*tx]) = make_uint2(u0, u1);
        }
    }
}

// ------------------------------------------------------------------
// Kernel 2 (R10/R13 version): stats, K ping-pong of 64-i tiles; em in smem;
// az fused epilogue.
// grid (NN/128, BB), 256 thr.
// smem: Q 2x18432 @0, K ping-pong 2x18432 @36864, em 64x128 f32 @73728, zi @106496
// ------------------------------------------------------------------
#define ST_K    36864
#define ST_EM   73728
#define ST_ZI   106496
#define ST_SMEM 107008

__global__ void __launch_bounds__(256) stats_kernel()
{
    extern __shared__ char smc[];
    const uint32_t sb = smem_to_u32(smc);
    float* sem = reinterpret_cast<float*>(smc + ST_EM);
    float* szi = reinterpret_cast<float*>(smc + ST_ZI);
    const int b = blockIdx.y, j0 = blockIdx.x * 128;
    const int t = threadIdx.x, w = t >> 5, lane = t & 31;
    const int lr = lane & 7, g = lane >> 3, qr = lane >> 2, qc = lane & 3;

    // prefetch K tiles 0,1
    #pragma unroll
    for (int pf = 0; pf < 2; pf++) {
        const uint32_t dH = sb + ST_K + pf*18432, dL = dH + 9216;
        const int i0n = pf * 64;
        #pragma unroll
        for (int p = 0; p < 2; p++) {
            int idx = t + p*256; int row = idx >> 3, seg = idx & 7;
            cp16(dH + row*BPITCH + seg*16, &g_kh[(size_t)(b*NN + i0n + row)*CC + seg*8]);
            cp16(dL + row*BPITCH + seg*16, &g_kl[(size_t)(b*NN + i0n + row)*CC + seg*8]);
        }
        CP_COMMIT();
    }

    {   // Q tiles (128 rows, plain loads)
        const __nv_bfloat16* sH = &g_qh[(size_t)(b*NN + j0)*CC];
        const __nv_bfloat16* sL = &g_ql[(size_t)(b*NN + j0)*CC];
        for (int idx = t; idx < 1024; idx += 256) {
            int row = idx >> 3, seg = idx & 7;
            *(uint4*)(smc + row*BPITCH + seg*16)         = *(const uint4*)&sH[row*64 + seg*8];
            *(uint4*)(smc + 18432 + row*BPITCH + seg*16) = *(const uint4*)&sL[row*64 + seg*8];
        }
    }
    __syncthreads();

    uint32_t Ah[4][4], Al[4][4];
    #pragma unroll
    for (int ks = 0; ks < 4; ks++) {
        ldsm4(addrA(sb,         w*16, ks*16, lr, g), Ah[ks]);
        ldsm4(addrA(sb + 18432, w*16, ks*16, lr, g), Al[ks]);
    }

    float zacc0 = 0.f, zacc1 = 0.f;
    const int jlo = j0 + w*16 + qr;

    for (int it = 0; it < NN/64; it++) {
        if (it < NN/64 - 1) CP_WAIT1(); else CP_WAIT0();
        __syncthreads();

        const uint32_t kbH = sb + ST_K + (it & 1)*18432, kbL = kbH + 9216;
        float C[8][4];
        #pragma unroll
        for (int nt = 0; nt < 8; nt++) {
            uint32_t bh[8], bl[8];
            ldsm4(addrB(kbH, nt*8,  0, lr, g), bh);
            ldsm4(addrB(kbH, nt*8, 32, lr, g), bh + 4);
            ldsm4(addrB(kbL, nt*8,  0, lr, g), bl);
            ldsm4(addrB(kbL, nt*8, 32, lr, g), bl + 4);
            C[nt][0] = C[nt][1] = C[nt][2] = C[nt][3] = 0.f;
            #pragma unroll
            for (int ks = 0; ks < 4; ks++) mma16816(C[nt], Ah[ks], bh[2*ks], bh[2*ks+1]);
            #pragma unroll
            for (int ks = 0; ks < 4; ks++) mma16816(C[nt], Ah[ks], bl[2*ks], bl[2*ks+1]);
            #pragma unroll
            for (int ks = 0; ks < 4; ks++) mma16816(C[nt], Al[ks], bh[2*ks], bh[2*ks+1]);
        }

        float pm0 = C[0][0], pm1 = C[0][2];
        #pragma unroll
        for (int nt = 0; nt < 8; nt++) {
            pm0 = fmaxf(pm0, fmaxf(C[nt][0], C[nt][1]));
            pm1 = fmaxf(pm1, fmaxf(C[nt][2], C[nt][3]));
        }
        pm0 = fmaxf(pm0, __shfl_xor_sync(0xffffffffu, pm0, 1));
        pm0 = fmaxf(pm0, __shfl_xor_sync(0xffffffffu, pm0, 2));
        pm1 = fmaxf(pm1, __shfl_xor_sync(0xffffffffu, pm1, 1));
        pm1 = fmaxf(pm1, __shfl_xor_sync(0xffffffffu, pm1, 2));
        const float em0 = __expf(pm0), em1 = __expf(pm1);

        float ps0 = 0.f, ps1 = 0.f;
        #pragma unroll
        for (int nt = 0; nt < 8; nt++) {
            C[nt][0] = __expf(C[nt][0] - pm0);
            C[nt][1] = __expf(C[nt][1] - pm0);
            C[nt][2] = __expf(C[nt][2] - pm1);
            C[nt][3] = __expf(C[nt][3] - pm1);
            ps0 += C[nt][0] + C[nt][1];
            ps1 += C[nt][2] + C[nt][3];
        }
        ps0 += __shfl_xor_sync(0xffffffffu, ps0, 1);
        ps0 += __shfl_xor_sync(0xffffffffu, ps0, 2);
        ps1 += __shfl_xor_sync(0xffffffffu, ps1, 1);
        ps1 += __shfl_xor_sync(0xffffffffu, ps1, 2);
        zacc0 += em0 * ps0;
        zacc1 += em1 * ps1;

        // coalesced permuted store
        const size_t rb0 = (size_t)(b*NN + jlo)*NN + it*64;
        const size_t rb1 = rb0 + (size_t)8*NN;
        #pragma unroll
        for (int pk = 0; pk < 2; pk++) {
            uint4 u0, u1;
            u0.x = packh2(C[pk*4+0][0], C[pk*4+0][1]);
            u0.y = packh2(C[pk*4+1][0], C[pk*4+1][1]);
            u0.z = packh2(C[pk*4+2][0], C[pk*4+2][1]);
            u0.w = packh2(C[pk*4+3][0], C[pk*4+3][1]);
            u1.x = packh2(C[pk*4+0][2], C[pk*4+0][3]);
            u1.y = packh2(C[pk*4+1][2], C[pk*4+1][3]);
            u1.z = packh2(C[pk*4+2][2], C[pk*4+2][3]);
            u1.w = packh2(C[pk*4+3][2], C[pk*4+3][3]);
            *(uint4*)&g_pf16[rb0 + pk*32 + qc*8] = u0;
            *(uint4*)&g_pf16[rb1 + pk*32 + qc*8] = u1;
        }
        if (qc == 0) {
            sem[it*128 + w*16 + qr]     = em0;
            sem[it*128 + w*16 + qr + 8] = em1;
        }
        __syncthreads();

        if (it + 2 < NN/64) {
            const uint32_t dH = sb + ST_K + (it & 1)*18432, dL = dH + 9216;
            const int i0n = (it + 2) * 64;
            #pragma unroll
            for (int p = 0; p < 2; p++) {
                int idx = t + p*256; int row = idx >> 3, seg = idx & 7;
                cp16(dH + row*BPITCH + seg*16, &g_kh[(size_t)(b*NN + i0n + row)*CC + seg*8]);
                cp16(dL + row*BPITCH + seg*16, &g_kl[(size_t)(b*NN + i0n + row)*CC + seg*8]);
            }
            CP_COMMIT();
        }
    }

    if (qc == 0) {
        szi[w*16 + qr]     = 1.f / zacc0;
        szi[w*16 + qr + 8] = 1.f / zacc1;
    }
    __syncthreads();

    // az epilogue from smem: az[t][j0+jl] = em[t][jl] * zi[jl]
    const int jl = t & 127, tg = t >> 7;
    const float zil = szi[jl];
    #pragma unroll 4
    for (int tt = tg; tt < 64; tt += 2)
        g_azh[(size_t)(b*64 + tt)*NN + j0 + jl] = __float2half_rn(sem[tt*128 + jl] * zil);
}

// ------------------------------------------------------------------
// Kernel 3: apply + fused output projection.
// grid (NN/128, BB), 256 thr. Stage = 128 j-rows.
// smem: P 2x34816 @0, V 2x18432 @69632, az 2x512 @106496
// Epilogue reuse: res tile [c][n] pitch RPITCH @0, Wo ws @34816
// ------------------------------------------------------------------
#define AP_VB   69632
#define AP_AZB  106496
#define AP_SMEM 107520

__global__ void __launch_bounds__(256) apply_kernel(const float* __restrict__ Wo,
                                                    const float* __restrict__ bo,
                                                    float* __restrict__ out)
{
    extern __shared__ char smc[];
    const uint32_t sb = smem_to_u32(smc);
    const int b = blockIdx.y, i0 = blockIdx.x * 128;
    const int t = threadIdx.x, w = t >> 5, lane = t & 31;
    const int lr = lane & 7, g = lane >> 3, qr = lane >> 2, qc = lane & 3;
    const int t0 = blockIdx.x * 2;   // stats tile index of first 64-i half

    // prologue: j-stages 0, 1 (128 rows each)
    #pragma unroll
    for (int pf = 0; pf < 2; pf++) {
        const uint32_t pb = sb + pf*34816;
        const uint32_t vb = sb + AP_VB + pf*18432;
        const uint32_t ab = sb + AP_AZB + pf*512;
        const int j0 = pf * 128;
        #pragma unroll
        for (int p = 0; p < 8; p++) {
            int idx = t + p*256; int row = idx >> 4, seg = idx & 15;
            cp16(pb + row*APITCH + seg*16, &g_pf16[((size_t)b*NN + j0 + row)*NN + i0 + seg*8]);
        }
        #pragma unroll
        for (int p = 0; p < 4; p++) {
            int idx = t + p*256; int row = idx >> 3, seg = idx & 7;
            cp16(vb + row*BPITCH + seg*16, &g_vf[(size_t)(b*NN + j0 + row)*CC + seg*8]);
        }
        if (t < 32)
            cp16(ab + t*16, &g_azh[(size_t)(b*64 + t0 + (t >> 4))*NN + j0 + (t & 15)*8]);
        CP_COMMIT();
    }

    float O[8][4];
    #pragma unroll
    for (int cn = 0; cn < 8; cn++)
        #pragma unroll
        for (int u = 0; u < 4; u++) O[cn][u] = 0.f;

    for (int jt = 0; jt < NN/128; jt++) {
        if (jt < NN/128 - 1) CP_WAIT1(); else CP_WAIT0();
        __syncthreads();

        const uint32_t pb = sb + (jt & 1)*34816;
        const uint32_t vb = sb + AP_VB + (jt & 1)*18432;
        const char* azp = smc + AP_AZB + (jt & 1)*512 + (w >> 2)*256;

        uint32_t A[8][4];
        #pragma unroll
        for (int ks = 0; ks < 8; ks++) {
            ldsm4t(addrAt(pb, w*16, ks*16, lr, g), A[ks]);
            uint32_t az01 = *(const uint32_t*)(azp + (ks*16 + 2*qc)*2);
            uint32_t az89 = *(const uint32_t*)(azp + (ks*16 + 2*qc + 8)*2);
            A[ks][0] = hmul2u(A[ks][0], az01);
            A[ks][1] = hmul2u(A[ks][1], az01);
            A[ks][2] = hmul2u(A[ks][2], az89);
            A[ks][3] = hmul2u(A[ks][3], az89);
        }
        #pragma unroll
        for (int cn = 0; cn < 8; cn++) {
            uint32_t vv[16];
            ldsm4t(addrBt(vb,  0, cn*8, lr, g), vv);
            ldsm4t(addrBt(vb, 32, cn*8, lr, g), vv + 4);
            ldsm4t(addrBt(vb, 64, cn*8, lr, g), vv + 8);
            ldsm4t(addrBt(vb, 96, cn*8, lr, g), vv + 12);
            #pragma unroll
            for (int ks = 0; ks < 8; ks++) mma16816h(O[cn], A[ks], vv[2*ks], vv[2*ks+1]);
        }
        __syncthreads();

        if (jt + 2 < NN/128) {
            const uint32_t dpb = sb + (jt & 1)*34816;
            const uint32_t dvb = sb + AP_VB + (jt & 1)*18432;
            const uint32_t dab = sb + AP_AZB + (jt & 1)*512;
            const int j0n = (jt + 2) * 128;
            #pragma unroll
            for (int p = 0; p < 8; p++) {
                int idx = t + p*256; int row = idx >> 4, seg = idx & 15;
                cp16(dpb + row*APITCH + seg*16, &g_pf16[((size_t)b*NN + j0n + row)*NN + i0 + seg*8]);
            }
            #pragma unroll
            for (int p = 0; p < 4; p++) {
                int idx = t + p*256; int row = idx >> 3, seg = idx & 7;
                cp16(dvb + row*BPITCH + seg*16, &g_vf[(size_t)(b*NN + j0n + row)*CC + seg*8]);
            }
            if (t < 32)
                cp16(dab + t*16, &g_azh[(size_t)(b*64 + t0 + (t >> 4))*NN + j0n + (t & 15)*8]);
            CP_COMMIT();
        }
    }

    // ---------- fused output projection ----------
    float* rstile = reinterpret_cast<float*>(smc);            // [c][n_local] pitch RPITCH
    float* wst    = reinterpret_cast<float*>(smc + 34816);    // [cin][cout] pitch PITCH

    {   // un-permute i' -> i, store O to smem transposed
        const int ia0 = swapbits(w*16 + qr);
        const int ia1 = swapbits(w*16 + qr + 8);
        #pragma unroll
        for (int cn = 0; cn < 8; cn++) {
            const int col = cn*8 + qc*2;
            rstile[(col    )*RPITCH + ia0] = O[cn][0];
            rstile[(col + 1)*RPITCH + ia0] = O[cn][1];
            rstile[(col    )*RPITCH + ia1] = O[cn][2];
            rstile[(col + 1)*RPITCH + ia1] = O[cn][3];
        }
    }
    for (int idx = t; idx < CC*CC; idx += 256) {
        int cout = idx >> 6, cin = idx & 63;
        wst[cin*PITCH + cout] = Wo[idx];
    }
    __syncthreads();

    const int tx = t & 15, ty = t >> 4;
    #pragma unroll
    for (int h = 0; h < 2; h++) {
        float acc[4][4];
        #pragma unroll
        for (int k = 0; k < 4; k++)
            #pragma unroll
            for (int j = 0; j < 4; j++) acc[k][j] = 0.f;

        #pragma unroll 4
        for (int ci = 0; ci < CC; ci++) {
            const float4 r4 = LD4(&rstile[ci*RPITCH + h*64 + 4*tx]);
            float wv[4];
            #pragma unroll
            for (int k = 0; k < 4; k++) wv[k] = wst[ci*PITCH + ty + 16*k];
            #pragma unroll
            for (int k = 0; k < 4; k++) {
                acc[k][0] = fmaf(wv[k], r4.x, acc[k][0]);
                acc[k][1] = fmaf(wv[k], r4.y, acc[k][1]);
                acc[k][2] = fmaf(wv[k], r4.z, acc[k][2]);
                acc[k][3] = fmaf(wv[k], r4.w, acc[k][3]);
            }
        }

        #pragma unroll
        for (int k = 0; k < 4; k++) {
            const int c = ty + 16*k;
            const float bvv = bo[c];
            const float4 resid = LD4(&rstile[c*RPITCH + h*64 + 4*tx]);
            float4 o;
            o.x = acc[k][0] + bvv + resid.x;
            o.y = acc[k][1] + bvv + resid.y;
            o.z = acc[k][2] + bvv + resid.z;
            o.w = acc[k][3] + bvv + resid.w;
            *(float4*)&out[(size_t)(b*CC + c)*NN + i0 + h*64 + 4*tx] = o;
        }
    }
}

// ------------------------------------------------------------------
extern "C" void kernel_launch(void* const* d_in, const int* in_sizes, int n_in,
                              void* d_out, int out_size)
{
    const float* x  = (const float*)d_in[0];
    const float* Wq = (const float*)d_in[1];
    const float* bq = (const float*)d_in[2];
    const float* Wk = (const float*)d_in[3];
    const float* bk = (const float*)d_in[4];
    const float* Wv = (const float*)d_in[5];
    const float* bv = (const float*)d_in[6];
    const float* Wo = (const float*)d_in[7];
    const float* bo = (const float*)d_in[8];
    float* out = (float*)d_out;

    cudaFuncSetAttribute(qkv_kernel,   cudaFuncAttributeMaxDynamicSharedMemorySize, QKV_SMEM);
    cudaFuncSetAttribute(stats_kernel, cudaFuncAttributeMaxDynamicSharedMemorySize, ST_SMEM);
    cudaFuncSetAttribute(apply_kernel, cudaFuncAttributeMaxDynamicSharedMemorySize, AP_SMEM);

    qkv_kernel<<<dim3(NN/256, BB), 256, QKV_SMEM>>>(x, Wq, bq, Wk, bk, Wv, bv);
    stats_kernel<<<dim3(NN/128, BB), 256, ST_SMEM>>>();
    apply_kernel<<<dim3(NN/128, BB), 256, AP_SMEM>>>(Wo, bo, out);
}

// round 16
// speedup vs baseline: 1.1980x; 1.0074x over previous
#include <cuda_runtime.h>
#include <cuda_bf16.h>
#include <cuda_fp16.h>
#include <cstdint>

#define BB 8
#define CC 64
#define NN 4096
#define PITCH 68      // fp32 smem pitch (qkv ws / apply ws)
#define RPITCH 132    // fp32 pitch for apply res tile (128 n + pad)
#define BPITCH 144    // bf16/fp16 tile pitch bytes (64 elems + pad)
#define APITCH 272    // apply P-tile pitch bytes (128 fp16 + pad)

// ---------------- scratch ----------------
__device__ __nv_bfloat16 g_qh[BB*NN*CC], g_ql[BB*NN*CC];
__device__ __nv_bfloat16 g_kh[BB*NN*CC], g_kl[BB*NN*CC];
__device__ __half g_vf[BB*NN*CC];                   // V fp16 [b][j][c]
__device__ __half g_pf16[(size_t)BB*NN*NN];         // P~ fp16 [b][j][i-permuted]
__device__ __half g_azh[(size_t)BB*64*NN];          // az = e^{m_t}/Z_j fp16 [b][t][j]

#define LD4(p) (*(const float4*)(p))

__device__ __forceinline__ uint32_t smem_to_u32(const void* p) {
    uint32_t a;
    asm("{ .reg .u64 t; cvta.to.shared.u64 t, %1; cvt.u32.u64 %0, t; }" : "=r"(a) : "l"(p));
    return a;
}
__device__ __forceinline__ void ldsm4(uint32_t addr, uint32_t* r) {
    asm volatile("ldmatrix.sync.aligned.m8n8.x4.shared.b16 {%0,%1,%2,%3}, [%4];"
                 : "=r"(r[0]), "=r"(r[1]), "=r"(r[2]), "=r"(r[3]) : "r"(addr));
}
__device__ __forceinline__ void ldsm4t(uint32_t addr, uint32_t* r) {
    asm volatile("ldmatrix.sync.aligned.m8n8.x4.trans.shared.b16 {%0,%1,%2,%3}, [%4];"
                 : "=r"(r[0]), "=r"(r[1]), "=r"(r[2]), "=r"(r[3]) : "r"(addr));
}
__device__ __forceinline__ void mma16816(float* c, const uint32_t* a, uint32_t b0, uint32_t b1) {
    asm volatile("mma.sync.aligned.m16n8k16.row.col.f32.bf16.bf16.f32 "
                 "{%0,%1,%2,%3}, {%4,%5,%6,%7}, {%8,%9}, {%0,%1,%2,%3};"
                 : "+f"(c[0]), "+f"(c[1]), "+f"(c[2]), "+f"(c[3])
                 : "r"(a[0]), "r"(a[1]), "r"(a[2]), "r"(a[3]), "r"(b0), "r"(b1));
}
__device__ __forceinline__ void mma16816h(float* c, const uint32_t* a, uint32_t b0, uint32_t b1) {
    asm volatile("mma.sync.aligned.m16n8k16.row.col.f32.f16.f16.f32 "
                 "{%0,%1,%2,%3}, {%4,%5,%6,%7}, {%8,%9}, {%0,%1,%2,%3};"
                 : "+f"(c[0]), "+f"(c[1]), "+f"(c[2]), "+f"(c[3])
                 : "r"(a[0]), "r"(a[1]), "r"(a[2]), "r"(a[3]), "r"(b0), "r"(b1));
}
__device__ __forceinline__ uint32_t packh2(float lo, float hi) {
    __half2 h = __floats2half2_rn(lo, hi);
    return *reinterpret_cast<uint32_t*>(&h);
}
__device__ __forceinline__ uint32_t hmul2u(uint32_t a, uint32_t b) {
    __half2 r = __hmul2(*reinterpret_cast<__half2*>(&a), *reinterpret_cast<__half2*>(&b));
    return *reinterpret_cast<uint32_t*>(&r);
}
__device__ __forceinline__ void split2(float p0, float p1, uint32_t& h, uint32_t& l) {
    __nv_bfloat16 h0 = __float2bfloat16_rn(p0), h1 = __float2bfloat16_rn(p1);
    __nv_bfloat16 l0 = __float2bfloat16_rn(p0 - __bfloat162float(h0));
    __nv_bfloat16 l1 = __float2bfloat16_rn(p1 - __bfloat162float(h1));
    h = ((uint32_t)__bfloat16_as_ushort(h1) << 16) | __bfloat16_as_ushort(h0);
    l = ((uint32_t)__bfloat16_as_ushort(l1) << 16) | __bfloat16_as_ushort(l0);
}
__device__ __forceinline__ void cp16(uint32_t saddr, const void* gaddr) {
    asm volatile("cp.async.cg.shared.global [%0], [%1], 16;" :: "r"(saddr), "l"(gaddr));
}
#define CP_COMMIT() asm volatile("cp.async.commit_group;" ::: "memory")
#define CP_WAIT0()  asm volatile("cp.async.wait_group 0;" ::: "memory")
#define CP_WAIT1()  asm volatile("cp.async.wait_group 1;" ::: "memory")

// A fragment m16k16 from [m][k] storage (pitch BPITCH)
__device__ __forceinline__ uint32_t addrA(uint32_t base, int r0, int c0, int lr, int g) {
    return base + (uint32_t)(r0 + lr + ((g & 1) << 3)) * BPITCH + ((uint32_t)(c0 + ((g >> 1) << 3)) << 1);
}
// B fragments from [n][k] storage
__device__ __forceinline__ uint32_t addrB(uint32_t base, int n0, int k0, int lr, int g) {
    return base + (uint32_t)(n0 + lr) * BPITCH + ((uint32_t)(k0 + g * 8) << 1);
}
// A fragment m16k16 via trans from [k][m] storage (pitch APITCH)
__device__ __forceinline__ uint32_t addrAt(uint32_t base, int m0, int k0, int lr, int g) {
    return base + (uint32_t)(k0 + ((g >> 1) << 3) + lr) * APITCH + ((uint32_t)(m0 + ((g & 1) << 3)) << 1);
}
// B fragments via trans from [k][n] storage (pitch BPITCH)
__device__ __forceinline__ uint32_t addrBt(uint32_t base, int k0, int n0, int lr, int g) {
    return base + (uint32_t)(k0 + g * 8 + lr) * BPITCH + ((uint32_t)n0 << 1);
}
// permutation: swap bits [4:3] <-> [2:1] (i within 64-tile; bit 6 preserved)
__device__ __forceinline__ int swapbits(int idx) {
    return (idx & 0x61) | ((idx & 0x18) >> 2) | ((idx & 0x06) << 2);
}

// ------------------------------------------------------------------
// Kernel 1: q,k -> bf16 hi/lo planes [b][n][c]; v -> fp16 [b][n][c]
// grid (NN/256, BB), 512 thr. Weights once; 2 x-tiles of 128 pixels, dbl-buf.
// smem: ws 3x64x68 f32 @0 (52224 B), xs 2x(64x128 f32 = 32768) @52224
// ------------------------------------------------------------------
#define QK_X     52224
#define QKV_SMEM 117760

__global__ void __launch_bounds__(512) qkv_kernel(const float* __restrict__ x,
                           const float* __restrict__ Wq, const float* __restrict__ bq,
                           const float* __restrict__ Wk, const float* __restrict__ bk,
                           const float* __restrict__ Wv, const float* __restrict__ bv)
{
    extern __shared__ char smc[];
    const uint32_t sb = smem_to_u32(smc);
    float* ws = reinterpret_cast<float*>(smc);
    const int b    = blockIdx.y;
    const int nb0  = blockIdx.x * 256;
    const int t    = threadIdx.x;

    // prefetch x tiles 0,1 (each: 64 cin rows x 128 n floats = 64 x 32 cp16)
    #pragma unroll
    for (int pf = 0; pf < 2; pf++) {
        const uint32_t dx = sb + QK_X + pf*32768;
        const int n0 = nb0 + pf*128;
        #pragma unroll
        for (int p = 0; p < 4; p++) {
            int idx = t + p*512; int cin = idx >> 5, seg = idx & 31;
            cp16(dx + cin*512 + seg*16, &x[(size_t)(b*CC + cin)*NN + n0 + seg*4]);
        }
        CP_COMMIT();
    }

    // weights (transposed) once
    const float* Wmats[3] = {Wq, Wk, Wv};
    #pragma unroll
    for (int m = 0; m < 3; m++)
        for (int idx = t; idx < CC*CC; idx += 512) {
            int cout = idx >> 6, cin = idx & 63;
            ws[(m*CC + cin)*PITCH + cout] = Wmats[m][idx];
        }

    const int tx = t & 15, ty = t >> 4;   // tx: cout group, ty: 0..31 pixel lane
    const float4 bq4 = LD4(&bq[4*tx]);
    const float4 bk4 = LD4(&bk[4*tx]);
    const float4 bv4 = LD4(&bv[4*tx]);
    const float bQ[4] = {bq4.x, bq4.y, bq4.z, bq4.w};
    const float bK[4] = {bk4.x, bk4.y, bk4.z, bk4.w};

    #pragma unroll
    for (int tt = 0; tt < 2; tt++) {
        if (tt < 1) CP_WAIT1(); else CP_WAIT0();
        __syncthreads();
        const float* xs = reinterpret_cast<const float*>(smc + QK_X + tt*32768);
        const int n0 = nb0 + tt*128;

        float acc[3][4][4];
        #pragma unroll
        for (int m = 0; m < 3; m++)
            #pragma unroll
            for (int k = 0; k < 4; k++)
                #pragma unroll
                for (int j = 0; j < 4; j++) acc[m][k][j] = 0.f;

        #pragma unroll 4
        for (int ci = 0; ci < CC; ci++) {
            float xv[4];
            #pragma unroll
            for (int k = 0; k < 4; k++) xv[k] = xs[ci*128 + ty + 32*k];
            #pragma unroll
            for (int m = 0; m < 3; m++) {
                const float4 w4 = LD4(&ws[(m*CC + ci)*PITCH + 4*tx]);
                #pragma unroll
                for (int k = 0; k < 4; k++) {
                    acc[m][k][0] = fmaf(xv[k], w4.x, acc[m][k][0]);
                    acc[m][k][1] = fmaf(xv[k], w4.y, acc[m][k][1]);
                    acc[m][k][2] = fmaf(xv[k], w4.z, acc[m][k][2]);
                    acc[m][k][3] = fmaf(xv[k], w4.w, acc[m][k][3]);
                }
            }
        }

        // epilogue: q,k bf16 hi/lo; v fp16
        const float* bArr[2] = {bQ, bK};
        __nv_bfloat16* outsH[2] = {g_qh, g_kh};
        __nv_bfloat16* outsL[2] = {g_ql, g_kl};
        #pragma unroll
        for (int m = 0; m < 2; m++) {
            #pragma unroll
            for (int k = 0; k < 4; k++) {
                int n = n0 + ty + 32*k;
                uint32_t Hp[2], Lp[2];
                #pragma unroll
                for (int jp = 0; jp < 2; jp++) {
                    float v0 = acc[m][k][2*jp]   + bArr[m][2*jp];
                    float v1 = acc[m][k][2*jp+1] + bArr[m][2*jp+1];
                    split2(v0, v1, Hp[jp], Lp[jp]);
                }
                size_t idx = (size_t)(b*NN + n)*CC + 4*tx;
                *reinterpret_cast<uint2*>(&outsH[m][idx]) = make_uint2(Hp[0], Hp[1]);
                *reinterpret_cast<uint2*>(&outsL[m][idx]) = make_uint2(Lp[0], Lp[1]);
            }
        }
        #pragma unroll
        for (int k = 0; k < 4; k++) {
            int n = n0 + ty + 32*k;
            uint32_t u0 = packh2(acc[2][k][0] + bv4.x, acc[2][k][1] + bv4.y);
            uint32_t u1 = packh2(acc[2][k][2] + bv4.z, acc[2][k][3] + bv4.w);
            *reinterpret_cast<uint2*>(&g_vf[(size_t)(b*NN + n)*CC + 4*tx]) = make_uint2(u0, u1);
        }
    }
}

// ------------------------------------------------------------------
// Kernel 2: stats, K ping-pong of 64-i tiles; em in smem; az fused epilogue.
// grid (NN/128, BB), 256 thr.
// smem: Q 2x18432 @0, K ping-pong 2x18432 @36864, em 64x128 f32 @73728, zi @106496
// ------------------------------------------------------------------
#define ST_K    36864
#define ST_EM   73728
#define ST_ZI   106496
#define ST_SMEM 107008

__global__ void __launch_bounds__(256) stats_kernel()
{
    extern __shared__ char smc[];
    const uint32_t sb = smem_to_u32(smc);
    float* sem = reinterpret_cast<float*>(smc + ST_EM);
    float* szi = reinterpret_cast<float*>(smc + ST_ZI);
    const int b = blockIdx.y, j0 = blockIdx.x * 128;
    const int t = threadIdx.x, w = t >> 5, lane = t & 31;
    const int lr = lane & 7, g = lane >> 3, qr = lane >> 2, qc = lane & 3;

    // prefetch K tiles 0,1
    #pragma unroll
    for (int pf = 0; pf < 2; pf++) {
        const uint32_t dH = sb + ST_K + pf*18432, dL = dH + 9216;
        const int i0n = pf * 64;
        #pragma unroll
        for (int p = 0; p < 2; p++) {
            int idx = t + p*256; int row = idx >> 3, seg = idx & 7;
            cp16(dH + row*BPITCH + seg*16, &g_kh[(size_t)(b*NN + i0n + row)*CC + seg*8]);
            cp16(dL + row*BPITCH + seg*16, &g_kl[(size_t)(b*NN + i0n + row)*CC + seg*8]);
        }
        CP_COMMIT();
    }

    {   // Q tiles (128 rows, plain loads)
        const __nv_bfloat16* sH = &g_qh[(size_t)(b*NN + j0)*CC];
        const __nv_bfloat16* sL = &g_ql[(size_t)(b*NN + j0)*CC];
        for (int idx = t; idx < 1024; idx += 256) {
            int row = idx >> 3, seg = idx & 7;
            *(uint4*)(smc + row*BPITCH + seg*16)         = *(const uint4*)&sH[row*64 + seg*8];
            *(uint4*)(smc + 18432 + row*BPITCH + seg*16) = *(const uint4*)&sL[row*64 + seg*8];
        }
    }
    __syncthreads();

    uint32_t Ah[4][4], Al[4][4];
    #pragma unroll
    for (int ks = 0; ks < 4; ks++) {
        ldsm4(addrA(sb,         w*16, ks*16, lr, g), Ah[ks]);
        ldsm4(addrA(sb + 18432, w*16, ks*16, lr, g), Al[ks]);
    }

    float zacc0 = 0.f, zacc1 = 0.f;
    const int jlo = j0 + w*16 + qr;

    for (int it = 0; it < NN/64; it++) {
        if (it < NN/64 - 1) CP_WAIT1(); else CP_WAIT0();
        __syncthreads();

        const uint32_t kbH = sb + ST_K + (it & 1)*18432, kbL = kbH + 9216;
        float C[8][4];
        #pragma unroll
        for (int nt = 0; nt < 8; nt++) {
            uint32_t bh[8], bl[8];
            ldsm4(addrB(kbH, nt*8,  0, lr, g), bh);
            ldsm4(addrB(kbH, nt*8, 32, lr, g), bh + 4);
            ldsm4(addrB(kbL, nt*8,  0, lr, g), bl);
            ldsm4(addrB(kbL, nt*8, 32, lr, g), bl + 4);
            C[nt][0] = C[nt][1] = C[nt][2] = C[nt][3] = 0.f;
            #pragma unroll
            for (int ks = 0; ks < 4; ks++) mma16816(C[nt], Ah[ks], bh[2*ks], bh[2*ks+1]);
            #pragma unroll
            for (int ks = 0; ks < 4; ks++) mma16816(C[nt], Ah[ks], bl[2*ks], bl[2*ks+1]);
            #pragma unroll
            for (int ks = 0; ks < 4; ks++) mma16816(C[nt], Al[ks], bh[2*ks], bh[2*ks+1]);
        }

        float pm0 = C[0][0], pm1 = C[0][2];
        #pragma unroll
        for (int nt = 0; nt < 8; nt++) {
            pm0 = fmaxf(pm0, fmaxf(C[nt][0], C[nt][1]));
            pm1 = fmaxf(pm1, fmaxf(C[nt][2], C[nt][3]));
        }
        pm0 = fmaxf(pm0, __shfl_xor_sync(0xffffffffu, pm0, 1));
        pm0 = fmaxf(pm0, __shfl_xor_sync(0xffffffffu, pm0, 2));
        pm1 = fmaxf(pm1, __shfl_xor_sync(0xffffffffu, pm1, 1));
        pm1 = fmaxf(pm1, __shfl_xor_sync(0xffffffffu, pm1, 2));
        const float em0 = __expf(pm0), em1 = __expf(pm1);

        float ps0 = 0.f, ps1 = 0.f;
        #pragma unroll
        for (int nt = 0; nt < 8; nt++) {
            C[nt][0] = __expf(C[nt][0] - pm0);
            C[nt][1] = __expf(C[nt][1] - pm0);
            C[nt][2] = __expf(C[nt][2] - pm1);
            C[nt][3] = __expf(C[nt][3] - pm1);
            ps0 += C[nt][0] + C[nt][1];
            ps1 += C[nt][2] + C[nt][3];
        }
        ps0 += __shfl_xor_sync(0xffffffffu, ps0, 1);
        ps0 += __shfl_xor_sync(0xffffffffu, ps0, 2);
        ps1 += __shfl_xor_sync(0xffffffffu, ps1, 1);
        ps1 += __shfl_xor_sync(0xffffffffu, ps1, 2);
        zacc0 += em0 * ps0;
        zacc1 += em1 * ps1;

        // coalesced permuted store
        const size_t rb0 = (size_t)(b*NN + jlo)*NN + it*64;
        const size_t rb1 = rb0 + (size_t)8*NN;
        #pragma unroll
        for (int pk = 0; pk < 2; pk++) {
            uint4 u0, u1;
            u0.x = packh2(C[pk*4+0][0], C[pk*4+0][1]);
            u0.y = packh2(C[pk*4+1][0], C[pk*4+1][1]);
            u0.z = packh2(C[pk*4+2][0], C[pk*4+2][1]);
            u0.w = packh2(C[pk*4+3][0], C[pk*4+3][1]);
            u1.x = packh2(C[pk*4+0][2], C[pk*4+0][3]);
            u1.y = packh2(C[pk*4+1][2], C[pk*4+1][3]);
            u1.z = packh2(C[pk*4+2][2], C[pk*4+2][3]);
            u1.w = packh2(C[pk*4+3][2], C[pk*4+3][3]);
            *(uint4*)&g_pf16[rb0 + pk*32 + qc*8] = u0;
            *(uint4*)&g_pf16[rb1 + pk*32 + qc*8] = u1;
        }
        if (qc == 0) {
            sem[it*128 + w*16 + qr]     = em0;
            sem[it*128 + w*16 + qr + 8] = em1;
        }
        __syncthreads();

        if (it + 2 < NN/64) {
            const uint32_t dH = sb + ST_K + (it & 1)*18432, dL = dH + 9216;
            const int i0n = (it + 2) * 64;
            #pragma unroll
            for (int p = 0; p < 2; p++) {
                int idx = t + p*256; int row = idx >> 3, seg = idx & 7;
                cp16(dH + row*BPITCH + seg*16, &g_kh[(size_t)(b*NN + i0n + row)*CC + seg*8]);
                cp16(dL + row*BPITCH + seg*16, &g_kl[(size_t)(b*NN + i0n + row)*CC + seg*8]);
            }
            CP_COMMIT();
        }
    }

    if (qc == 0) {
        szi[w*16 + qr]     = 1.f / zacc0;
        szi[w*16 + qr + 8] = 1.f / zacc1;
    }
    __syncthreads();

    // az epilogue from smem: az[t][j0+jl] = em[t][jl] * zi[jl]
    const int jl = t & 127, tg = t >> 7;
    const float zil = szi[jl];
    #pragma unroll 4
    for (int tt = tg; tt < 64; tt += 2)
        g_azh[(size_t)(b*64 + tt)*NN + j0 + jl] = __float2half_rn(sem[tt*128 + jl] * zil);
}

// ------------------------------------------------------------------
// Kernel 3: apply + fused output projection.
// grid (NN/128, BB), 256 thr. Stage = 128 j-rows.
// smem: P 2x34816 @0, V 2x18432 @69632, az 2x512 @106496
// Epilogue reuse: res tile [c][n] pitch RPITCH @0, Wo ws @34816
// ------------------------------------------------------------------
#define AP_VB   69632
#define AP_AZB  106496
#define AP_SMEM 107520

__global__ void __launch_bounds__(256) apply_kernel(const float* __restrict__ Wo,
                                                    const float* __restrict__ bo,
                                                    float* __restrict__ out)
{
    extern __shared__ char smc[];
    const uint32_t sb = smem_to_u32(smc);
    const int b = blockIdx.y, i0 = blockIdx.x * 128;
    const int t = threadIdx.x, w = t >> 5, lane = t & 31;
    const int lr = lane & 7, g = lane >> 3, qr = lane >> 2, qc = lane & 3;
    const int t0 = blockIdx.x * 2;   // stats tile index of first 64-i half

    // prologue: j-stages 0, 1 (128 rows each)
    #pragma unroll
    for (int pf = 0; pf < 2; pf++) {
        const uint32_t pb = sb + pf*34816;
        const uint32_t vb = sb + AP_VB + pf*18432;
        const uint32_t ab = sb + AP_AZB + pf*512;
        const int j0 = pf * 128;
        #pragma unroll
        for (int p = 0; p < 8; p++) {
            int idx = t + p*256; int row = idx >> 4, seg = idx & 15;
            cp16(pb + row*APITCH + seg*16, &g_pf16[((size_t)b*NN + j0 + row)*NN + i0 + seg*8]);
        }
        #pragma unroll
        for (int p = 0; p < 4; p++) {
            int idx = t + p*256; int row = idx >> 3, seg = idx & 7;
            cp16(vb + row*BPITCH + seg*16, &g_vf[(size_t)(b*NN + j0 + row)*CC + seg*8]);
        }
        if (t < 32)
            cp16(ab + t*16, &g_azh[(size_t)(b*64 + t0 + (t >> 4))*NN + j0 + (t & 15)*8]);
        CP_COMMIT();
    }

    float O[8][4];
    #pragma unroll
    for (int cn = 0; cn < 8; cn++)
        #pragma unroll
        for (int u = 0; u < 4; u++) O[cn][u] = 0.f;

    for (int jt = 0; jt < NN/128; jt++) {
        if (jt < NN/128 - 1) CP_WAIT1(); else CP_WAIT0();
        __syncthreads();

        const uint32_t pb = sb + (jt & 1)*34816;
        const uint32_t vb = sb + AP_VB + (jt & 1)*18432;
        const char* azp = smc + AP_AZB + (jt & 1)*512 + (w >> 2)*256;

        uint32_t A[8][4];
        #pragma unroll
        for (int ks = 0; ks < 8; ks++) {
            ldsm4t(addrAt(pb, w*16, ks*16, lr, g), A[ks]);
            uint32_t az01 = *(const uint32_t*)(azp + (ks*16 + 2*qc)*2);
            uint32_t az89 = *(const uint32_t*)(azp + (ks*16 + 2*qc + 8)*2);
            A[ks][0] = hmul2u(A[ks][0], az01);
            A[ks][1] = hmul2u(A[ks][1], az01);
            A[ks][2] = hmul2u(A[ks][2], az89);
            A[ks][3] = hmul2u(A[ks][3], az89);
        }
        #pragma unroll
        for (int cn = 0; cn < 8; cn++) {
            uint32_t vv[16];
            ldsm4t(addrBt(vb,  0, cn*8, lr, g), vv);
            ldsm4t(addrBt(vb, 32, cn*8, lr, g), vv + 4);
            ldsm4t(addrBt(vb, 64, cn*8, lr, g), vv + 8);
            ldsm4t(addrBt(vb, 96, cn*8, lr, g), vv + 12);
            #pragma unroll
            for (int ks = 0; ks < 8; ks++) mma16816h(O[cn], A[ks], vv[2*ks], vv[2*ks+1]);
        }
        __syncthreads();

        if (jt + 2 < NN/128) {
            const uint32_t dpb = sb + (jt & 1)*34816;
            const uint32_t dvb = sb + AP_VB + (jt & 1)*18432;
            const uint32_t dab = sb + AP_AZB + (jt & 1)*512;
            const int j0n = (jt + 2) * 128;
            #pragma unroll
            for (int p = 0; p < 8; p++) {
                int idx = t + p*256; int row = idx >> 4, seg = idx & 15;
                cp16(dpb + row*APITCH + seg*16, &g_pf16[((size_t)b*NN + j0n + row)*NN + i0 + seg*8]);
            }
            #pragma unroll
            for (int p = 0; p < 4; p++) {
                int idx = t + p*256; int row = idx >> 3, seg = idx & 7;
                cp16(dvb + row*BPITCH + seg*16, &g_vf[(size_t)(b*NN + j0n + row)*CC + seg*8]);
            }
            if (t < 32)
                cp16(dab + t*16, &g_azh[(size_t)(b*64 + t0 + (t >> 4))*NN + j0n + (t & 15)*8]);
            CP_COMMIT();
        }
    }

    // ---------- fused output projection ----------
    float* rstile = reinterpret_cast<float*>(smc);            // [c][n_local] pitch RPITCH
    float* wst    = reinterpret_cast<float*>(smc + 34816);    // [cin][cout] pitch PITCH

    {   // un-permute i' -> i, store O to smem transposed
        const int ia0 = swapbits(w*16 + qr);
        const int ia1 = swapbits(w*16 + qr + 8);
        #pragma unroll
        for (int cn = 0; cn < 8; cn++) {
            const int col = cn*8 + qc*2;
            rstile[(col    )*RPITCH + ia0] = O[cn][0];
            rstile[(col + 1)*RPITCH + ia0] = O[cn][1];
            rstile[(col    )*RPITCH + ia1] = O[cn][2];
            rstile[(col + 1)*RPITCH + ia1] = O[cn][3];
        }
    }
    for (int idx = t; idx < CC*CC; idx += 256) {
        int cout = idx >> 6, cin = idx & 63;
        wst[cin*PITCH + cout] = Wo[idx];
    }
    __syncthreads();

    const int tx = t & 15, ty = t >> 4;
    #pragma unroll
    for (int h = 0; h < 2; h++) {
        float acc[4][4];
        #pragma unroll
        for (int k = 0; k < 4; k++)
            #pragma unroll
            for (int j = 0; j < 4; j++) acc[k][j] = 0.f;

        #pragma unroll 4
        for (int ci = 0; ci < CC; ci++) {
            const float4 r4 = LD4(&rstile[ci*RPITCH + h*64 + 4*tx]);
            float wv[4];
            #pragma unroll
            for (int k = 0; k < 4; k++) wv[k] = wst[ci*PITCH + ty + 16*k];
            #pragma unroll
            for (int k = 0; k < 4; k++) {
                acc[k][0] = fmaf(wv[k], r4.x, acc[k][0]);
                acc[k][1] = fmaf(wv[k], r4.y, acc[k][1]);
                acc[k][2] = fmaf(wv[k], r4.z, acc[k][2]);
                acc[k][3] = fmaf(wv[k], r4.w, acc[k][3]);
            }
        }

        #pragma unroll
        for (int k = 0; k < 4; k++) {
            const int c = ty + 16*k;
            const float bvv = bo[c];
            const float4 resid = LD4(&rstile[c*RPITCH + h*64 + 4*tx]);
            float4 o;
            o.x = acc[k][0] + bvv + resid.x;
            o.y = acc[k][1] + bvv + resid.y;
            o.z = acc[k][2] + bvv + resid.z;
            o.w = acc[k][3] + bvv + resid.w;
            *(float4*)&out[(size_t)(b*CC + c)*NN + i0 + h*64 + 4*tx] = o;
        }
    }
}

// ------------------------------------------------------------------
extern "C" void kernel_launch(void* const* d_in, const int* in_sizes, int n_in,
                              void* d_out, int out_size)
{
    const float* x  = (const float*)d_in[0];
    const float* Wq = (const float*)d_in[1];
    const float* bq = (const float*)d_in[2];
    const float* Wk = (const float*)d_in[3];
    const float* bk = (const float*)d_in[4];
    const float* Wv = (const float*)d_in[5];
    const float* bv = (const float*)d_in[6];
    const float* Wo = (const float*)d_in[7];
    const float* bo = (const float*)d_in[8];
    float* out = (float*)d_out;

    cudaFuncSetAttribute(qkv_kernel,   cudaFuncAttributeMaxDynamicSharedMemorySize, QKV_SMEM);
    cudaFuncSetAttribute(stats_kernel, cudaFuncAttributeMaxDynamicSharedMemorySize, ST_SMEM);
    cudaFuncSetAttribute(apply_kernel, cudaFuncAttributeMaxDynamicSharedMemorySize, AP_SMEM);

    qkv_kernel<<<dim3(NN/256, BB), 512, QKV_SMEM>>>(x, Wq, bq, Wk, bk, Wv, bv);
    stats_kernel<<<dim3(NN/128, BB), 256, ST_SMEM>>>();
    apply_kernel<<<dim3(NN/128, BB), 256, AP_SMEM>>>(Wo, bo, out);
}

// round 17
// speedup vs baseline: 1.2086x; 1.0089x over previous
#include <cuda_runtime.h>
#include <cuda_bf16.h>
#include <cuda_fp16.h>
#include <cstdint>

#define BB 8
#define CC 64
#define NN 4096
#define PITCH 68      // fp32 smem pitch (qkv ws / apply ws)
#define RPITCH 132    // fp32 pitch for apply res tile (128 n + pad)
#define BPITCH 144    // bf16/fp16 tile pitch bytes (64 elems + pad)
#define APITCH 272    // apply P-tile pitch bytes (128 fp16 + pad)
#define LOG2E 1.4426950408889634f

// ---------------- scratch ----------------
__device__ __nv_bfloat16 g_qh[BB*NN*CC], g_ql[BB*NN*CC];   // q pre-scaled by log2(e)
__device__ __nv_bfloat16 g_kh[BB*NN*CC], g_kl[BB*NN*CC];
__device__ __half g_vf[BB*NN*CC];                   // V fp16 [b][j][c]
__device__ __half g_pf16[(size_t)BB*NN*NN];         // P~ fp16 [b][j][i-permuted]
__device__ __half g_azh[(size_t)BB*64*NN];          // az = e^{m_t}/Z_j fp16 [b][t][j]

#define LD4(p) (*(const float4*)(p))

__device__ __forceinline__ uint32_t smem_to_u32(const void* p) {
    uint32_t a;
    asm("{ .reg .u64 t; cvta.to.shared.u64 t, %1; cvt.u32.u64 %0, t; }" : "=r"(a) : "l"(p));
    return a;
}
__device__ __forceinline__ void ldsm4(uint32_t addr, uint32_t* r) {
    asm volatile("ldmatrix.sync.aligned.m8n8.x4.shared.b16 {%0,%1,%2,%3}, [%4];"
                 : "=r"(r[0]), "=r"(r[1]), "=r"(r[2]), "=r"(r[3]) : "r"(addr));
}
__device__ __forceinline__ void ldsm4t(uint32_t addr, uint32_t* r) {
    asm volatile("ldmatrix.sync.aligned.m8n8.x4.trans.shared.b16 {%0,%1,%2,%3}, [%4];"
                 : "=r"(r[0]), "=r"(r[1]), "=r"(r[2]), "=r"(r[3]) : "r"(addr));
}
__device__ __forceinline__ void mma16816(float* c, const uint32_t* a, uint32_t b0, uint32_t b1) {
    asm volatile("mma.sync.aligned.m16n8k16.row.col.f32.bf16.bf16.f32 "
                 "{%0,%1,%2,%3}, {%4,%5,%6,%7}, {%8,%9}, {%0,%1,%2,%3};"
                 : "+f"(c[0]), "+f"(c[1]), "+f"(c[2]), "+f"(c[3])
                 : "r"(a[0]), "r"(a[1]), "r"(a[2]), "r"(a[3]), "r"(b0), "r"(b1));
}
__device__ __forceinline__ void mma16816h(float* c, const uint32_t* a, uint32_t b0, uint32_t b1) {
    asm volatile("mma.sync.aligned.m16n8k16.row.col.f32.f16.f16.f32 "
                 "{%0,%1,%2,%3}, {%4,%5,%6,%7}, {%8,%9}, {%0,%1,%2,%3};"
                 : "+f"(c[0]), "+f"(c[1]), "+f"(c[2]), "+f"(c[3])
                 : "r"(a[0]), "r"(a[1]), "r"(a[2]), "r"(a[3]), "r"(b0), "r"(b1));
}
__device__ __forceinline__ uint32_t packh2(float lo, float hi) {
    __half2 h = __floats2half2_rn(lo, hi);
    return *reinterpret_cast<uint32_t*>(&h);
}
__device__ __forceinline__ uint32_t hmul2u(uint32_t a, uint32_t b) {
    __half2 r = __hmul2(*reinterpret_cast<__half2*>(&a), *reinterpret_cast<__half2*>(&b));
    return *reinterpret_cast<uint32_t*>(&r);
}
__device__ __forceinline__ float ex2(float x) {
    float r;
    asm("ex2.approx.f32 %0, %1;" : "=f"(r) : "f"(x));
    return r;
}
__device__ __forceinline__ void split2(float p0, float p1, uint32_t& h, uint32_t& l) {
    __nv_bfloat16 h0 = __float2bfloat16_rn(p0), h1 = __float2bfloat16_rn(p1);
    __nv_bfloat16 l0 = __float2bfloat16_rn(p0 - __bfloat162float(h0));
    __nv_bfloat16 l1 = __float2bfloat16_rn(p1 - __bfloat162float(h1));
    h = ((uint32_t)__bfloat16_as_ushort(h1) << 16) | __bfloat16_as_ushort(h0);
    l = ((uint32_t)__bfloat16_as_ushort(l1) << 16) | __bfloat16_as_ushort(l0);
}
__device__ __forceinline__ void cp16(uint32_t saddr, const void* gaddr) {
    asm volatile("cp.async.cg.shared.global [%0], [%1], 16;" :: "r"(saddr), "l"(gaddr));
}
#define CP_COMMIT() asm volatile("cp.async.commit_group;" ::: "memory")
#define CP_WAIT0()  asm volatile("cp.async.wait_group 0;" ::: "memory")
#define CP_WAIT1()  asm volatile("cp.async.wait_group 1;" ::: "memory")

// A fragment m16k16 from [m][k] storage (pitch BPITCH)
__device__ __forceinline__ uint32_t addrA(uint32_t base, int r0, int c0, int lr, int g) {
    return base + (uint32_t)(r0 + lr + ((g & 1) << 3)) * BPITCH + ((uint32_t)(c0 + ((g >> 1) << 3)) << 1);
}
// B fragments from [n][k] storage
__device__ __forceinline__ uint32_t addrB(uint32_t base, int n0, int k0, int lr, int g) {
    return base + (uint32_t)(n0 + lr) * BPITCH + ((uint32_t)(k0 + g * 8) << 1);
}
// A fragment m16k16 via trans from [k][m] storage (pitch APITCH)
__device__ __forceinline__ uint32_t addrAt(uint32_t base, int m0, int k0, int lr, int g) {
    return base + (uint32_t)(k0 + ((g >> 1) << 3) + lr) * APITCH + ((uint32_t)(m0 + ((g & 1) << 3)) << 1);
}
// B fragments via trans from [k][n] storage (pitch BPITCH)
__device__ __forceinline__ uint32_t addrBt(uint32_t base, int k0, int n0, int lr, int g) {
    return base + (uint32_t)(k0 + g * 8 + lr) * BPITCH + ((uint32_t)n0 << 1);
}
// permutation: swap bits [4:3] <-> [2:1] (i within 64-tile; bit 6 preserved)
__device__ __forceinline__ int swapbits(int idx) {
    return (idx & 0x61) | ((idx & 0x18) >> 2) | ((idx & 0x06) << 2);
}

// ------------------------------------------------------------------
// Kernel 1: q (pre-scaled by log2e), k -> bf16 hi/lo planes; v -> fp16
// grid (NN/256, BB), 512 thr.
// ------------------------------------------------------------------
#define QK_X     52224
#define QKV_SMEM 117760

__global__ void __launch_bounds__(512) qkv_kernel(const float* __restrict__ x,
                           const float* __restrict__ Wq, const float* __restrict__ bq,
                           const float* __restrict__ Wk, const float* __restrict__ bk,
                           const float* __restrict__ Wv, const float* __restrict__ bv)
{
    extern __shared__ char smc[];
    const uint32_t sb = smem_to_u32(smc);
    float* ws = reinterpret_cast<float*>(smc);
    const int b    = blockIdx.y;
    const int nb0  = blockIdx.x * 256;
    const int t    = threadIdx.x;

    #pragma unroll
    for (int pf = 0; pf < 2; pf++) {
        const uint32_t dx = sb + QK_X + pf*32768;
        const int n0 = nb0 + pf*128;
        #pragma unroll
        for (int p = 0; p < 4; p++) {
            int idx = t + p*512; int cin = idx >> 5, seg = idx & 31;
            cp16(dx + cin*512 + seg*16, &x[(size_t)(b*CC + cin)*NN + n0 + seg*4]);
        }
        CP_COMMIT();
    }

    const float* Wmats[3] = {Wq, Wk, Wv};
    #pragma unroll
    for (int m = 0; m < 3; m++)
        for (int idx = t; idx < CC*CC; idx += 512) {
            int cout = idx >> 6, cin = idx & 63;
            ws[(m*CC + cin)*PITCH + cout] = Wmats[m][idx];
        }

    const int tx = t & 15, ty = t >> 4;
    const float4 bq4 = LD4(&bq[4*tx]);
    const float4 bk4 = LD4(&bk[4*tx]);
    const float4 bv4 = LD4(&bv[4*tx]);
    const float bQ[4] = {bq4.x, bq4.y, bq4.z, bq4.w};
    const float bK[4] = {bk4.x, bk4.y, bk4.z, bk4.w};

    #pragma unroll
    for (int tt = 0; tt < 2; tt++) {
        if (tt < 1) CP_WAIT1(); else CP_WAIT0();
        __syncthreads();
        const float* xs = reinterpret_cast<const float*>(smc + QK_X + tt*32768);
        const int n0 = nb0 + tt*128;

        float acc[3][4][4];
        #pragma unroll
        for (int m = 0; m < 3; m++)
            #pragma unroll
            for (int k = 0; k < 4; k++)
                #pragma unroll
                for (int j = 0; j < 4; j++) acc[m][k][j] = 0.f;

        #pragma unroll 4
        for (int ci = 0; ci < CC; ci++) {
            float xv[4];
            #pragma unroll
            for (int k = 0; k < 4; k++) xv[k] = xs[ci*128 + ty + 32*k];
            #pragma unroll
            for (int m = 0; m < 3; m++) {
                const float4 w4 = LD4(&ws[(m*CC + ci)*PITCH + 4*tx]);
                #pragma unroll
                for (int k = 0; k < 4; k++) {
                    acc[m][k][0] = fmaf(xv[k], w4.x, acc[m][k][0]);
                    acc[m][k][1] = fmaf(xv[k], w4.y, acc[m][k][1]);
                    acc[m][k][2] = fmaf(xv[k], w4.z, acc[m][k][2]);
                    acc[m][k][3] = fmaf(xv[k], w4.w, acc[m][k][3]);
                }
            }
        }

        // epilogue: q scaled by log2e; q,k bf16 hi/lo; v fp16
        const float* bArr[2] = {bQ, bK};
        const float scl[2] = {LOG2E, 1.0f};
        __nv_bfloat16* outsH[2] = {g_qh, g_kh};
        __nv_bfloat16* outsL[2] = {g_ql, g_kl};
        #pragma unroll
        for (int m = 0; m < 2; m++) {
            #pragma unroll
            for (int k = 0; k < 4; k++) {
                int n = n0 + ty + 32*k;
                uint32_t Hp[2], Lp[2];
                #pragma unroll
                for (int jp = 0; jp < 2; jp++) {
                    float v0 = (acc[m][k][2*jp]   + bArr[m][2*jp])   * scl[m];
                    float v1 = (acc[m][k][2*jp+1] + bArr[m][2*jp+1]) * scl[m];
                    split2(v0, v1, Hp[jp], Lp[jp]);
                }
                size_t idx = (size_t)(b*NN + n)*CC + 4*tx;
                *reinterpret_cast<uint2*>(&outsH[m][idx]) = make_uint2(Hp[0], Hp[1]);
                *reinterpret_cast<uint2*>(&outsL[m][idx]) = make_uint2(Lp[0], Lp[1]);
            }
        }
        #pragma unroll
        for (int k = 0; k < 4; k++) {
            int n = n0 + ty + 32*k;
            uint32_t u0 = packh2(acc[2][k][0] + bv4.x, acc[2][k][1] + bv4.y);
            uint32_t u1 = packh2(acc[2][k][2] + bv4.z, acc[2][k][3] + bv4.w);
            *reinterpret_cast<uint2*>(&g_vf[(size_t)(b*NN + n)*CC + 4*tx]) = make_uint2(u0, u1);
        }
    }
}

// ------------------------------------------------------------------
// Kernel 2: stats (S' = S*log2e from pre-scaled q; all exps are bare ex2)
// grid (NN/128, BB), 256 thr.
// ------------------------------------------------------------------
#define ST_K    36864
#define ST_EM   73728
#define ST_ZI   106496
#define ST_SMEM 107008

__global__ void __launch_bounds__(256) stats_kernel()
{
    extern __shared__ char smc[];
    const uint32_t sb = smem_to_u32(smc);
    float* sem = reinterpret_cast<float*>(smc + ST_EM);
    float* szi = reinterpret_cast<float*>(smc + ST_ZI);
    const int b = blockIdx.y, j0 = blockIdx.x * 128;
    const int t = threadIdx.x, w = t >> 5, lane = t & 31;
    const int lr = lane & 7, g = lane >> 3, qr = lane >> 2, qc = lane & 3;

    #pragma unroll
    for (int pf = 0; pf < 2; pf++) {
        const uint32_t dH = sb + ST_K + pf*18432, dL = dH + 9216;
        const int i0n = pf * 64;
        #pragma unroll
        for (int p = 0; p < 2; p++) {
            int idx = t + p*256; int row = idx >> 3, seg = idx & 7;
            cp16(dH + row*BPITCH + seg*16, &g_kh[(size_t)(b*NN + i0n + row)*CC + seg*8]);
            cp16(dL + row*BPITCH + seg*16, &g_kl[(size_t)(b*NN + i0n + row)*CC + seg*8]);
        }
        CP_COMMIT();
    }

    {
        const __nv_bfloat16* sH = &g_qh[(size_t)(b*NN + j0)*CC];
        const __nv_bfloat16* sL = &g_ql[(size_t)(b*NN + j0)*CC];
        for (int idx = t; idx < 1024; idx += 256) {
            int row = idx >> 3, seg = idx & 7;
            *(uint4*)(smc + row*BPITCH + seg*16)         = *(const uint4*)&sH[row*64 + seg*8];
            *(uint4*)(smc + 18432 + row*BPITCH + seg*16) = *(const uint4*)&sL[row*64 + seg*8];
        }
    }
    __syncthreads();

    uint32_t Ah[4][4], Al[4][4];
    #pragma unroll
    for (int ks = 0; ks < 4; ks++) {
        ldsm4(addrA(sb,         w*16, ks*16, lr, g), Ah[ks]);
        ldsm4(addrA(sb + 18432, w*16, ks*16, lr, g), Al[ks]);
    }

    float zacc0 = 0.f, zacc1 = 0.f;
    const int jlo = j0 + w*16 + qr;

    for (int it = 0; it < NN/64; it++) {
        if (it < NN/64 - 1) CP_WAIT1(); else CP_WAIT0();
        __syncthreads();

        const uint32_t kbH = sb + ST_K + (it & 1)*18432, kbL = kbH + 9216;
        float C[8][4];
        #pragma unroll
        for (int nt = 0; nt < 8; nt++) {
            uint32_t bh[8], bl[8];
            ldsm4(addrB(kbH, nt*8,  0, lr, g), bh);
            ldsm4(addrB(kbH, nt*8, 32, lr, g), bh + 4);
            ldsm4(addrB(kbL, nt*8,  0, lr, g), bl);
            ldsm4(addrB(kbL, nt*8, 32, lr, g), bl + 4);
            C[nt][0] = C[nt][1] = C[nt][2] = C[nt][3] = 0.f;
            #pragma unroll
            for (int ks = 0; ks < 4; ks++) mma16816(C[nt], Ah[ks], bh[2*ks], bh[2*ks+1]);
            #pragma unroll
            for (int ks = 0; ks < 4; ks++) mma16816(C[nt], Ah[ks], bl[2*ks], bl[2*ks+1]);
            #pragma unroll
            for (int ks = 0; ks < 4; ks++) mma16816(C[nt], Al[ks], bh[2*ks], bh[2*ks+1]);
        }

        float pm0 = C[0][0], pm1 = C[0][2];
        #pragma unroll
        for (int nt = 0; nt < 8; nt++) {
            pm0 = fmaxf(pm0, fmaxf(C[nt][0], C[nt][1]));
            pm1 = fmaxf(pm1, fmaxf(C[nt][2], C[nt][3]));
        }
        pm0 = fmaxf(pm0, __shfl_xor_sync(0xffffffffu, pm0, 1));
        pm0 = fmaxf(pm0, __shfl_xor_sync(0xffffffffu, pm0, 2));
        pm1 = fmaxf(pm1, __shfl_xor_sync(0xffffffffu, pm1, 1));
        pm1 = fmaxf(pm1, __shfl_xor_sync(0xffffffffu, pm1, 2));
        const float em0 = ex2(pm0), em1 = ex2(pm1);

        float ps0 = 0.f, ps1 = 0.f;
        #pragma unroll
        for (int nt = 0; nt < 8; nt++) {
            C[nt][0] = ex2(C[nt][0] - pm0);
            C[nt][1] = ex2(C[nt][1] - pm0);
            C[nt][2] = ex2(C[nt][2] - pm1);
            C[nt][3] = ex2(C[nt][3] - pm1);
            ps0 += C[nt][0] + C[nt][1];
            ps1 += C[nt][2] + C[nt][3];
        }
        ps0 += __shfl_xor_sync(0xffffffffu, ps0, 1);
        ps0 += __shfl_xor_sync(0xffffffffu, ps0, 2);
        ps1 += __shfl_xor_sync(0xffffffffu, ps1, 1);
        ps1 += __shfl_xor_sync(0xffffffffu, ps1, 2);
        zacc0 += em0 * ps0;
        zacc1 += em1 * ps1;

        const size_t rb0 = (size_t)(b*NN + jlo)*NN + it*64;
        const size_t rb1 = rb0 + (size_t)8*NN;
        #pragma unroll
        for (int pk = 0; pk < 2; pk++) {
            uint4 u0, u1;
            u0.x = packh2(C[pk*4+0][0], C[pk*4+0][1]);
            u0.y = packh2(C[pk*4+1][0], C[pk*4+1][1]);
            u0.z = packh2(C[pk*4+2][0], C[pk*4+2][1]);
            u0.w = packh2(C[pk*4+3][0], C[pk*4+3][1]);
            u1.x = packh2(C[pk*4+0][2], C[pk*4+0][3]);
            u1.y = packh2(C[pk*4+1][2], C[pk*4+1][3]);
            u1.z = packh2(C[pk*4+2][2], C[pk*4+2][3]);
            u1.w = packh2(C[pk*4+3][2], C[pk*4+3][3]);
            *(uint4*)&g_pf16[rb0 + pk*32 + qc*8] = u0;
            *(uint4*)&g_pf16[rb1 + pk*32 + qc*8] = u1;
        }
        if (qc == 0) {
            sem[it*128 + w*16 + qr]     = em0;
            sem[it*128 + w*16 + qr + 8] = em1;
        }
        __syncthreads();

        if (it + 2 < NN/64) {
            const uint32_t dH = sb + ST_K + (it & 1)*18432, dL = dH + 9216;
            const int i0n = (it + 2) * 64;
            #pragma unroll
            for (int p = 0; p < 2; p++) {
                int idx = t + p*256; int row = idx >> 3, seg = idx & 7;
                cp16(dH + row*BPITCH + seg*16, &g_kh[(size_t)(b*NN + i0n + row)*CC + seg*8]);
                cp16(dL + row*BPITCH + seg*16, &g_kl[(size_t)(b*NN + i0n + row)*CC + seg*8]);
            }
            CP_COMMIT();
        }
    }

    if (qc == 0) {
        szi[w*16 + qr]     = 1.f / zacc0;
        szi[w*16 + qr + 8] = 1.f / zacc1;
    }
    __syncthreads();

    const int jl = t & 127, tg = t >> 7;
    const float zil = szi[jl];
    #pragma unroll 4
    for (int tt = tg; tt < 64; tt += 2)
        g_azh[(size_t)(b*64 + tt)*NN + j0 + jl] = __float2half_rn(sem[tt*128 + jl] * zil);
}

// ------------------------------------------------------------------
// Kernel 3: apply + fused output projection (unchanged from R15/16)
// ------------------------------------------------------------------
#define AP_VB   69632
#define AP_AZB  106496
#define AP_SMEM 107520

__global__ void __launch_bounds__(256) apply_kernel(const float* __restrict__ Wo,
                                                    const float* __restrict__ bo,
                                                    float* __restrict__ out)
{
    extern __shared__ char smc[];
    const uint32_t sb = smem_to_u32(smc);
    const int b = blockIdx.y, i0 = blockIdx.x * 128;
    const int t = threadIdx.x, w = t >> 5, lane = t & 31;
    const int lr = lane & 7, g = lane >> 3, qr = lane >> 2, qc = lane & 3;
    const int t0 = blockIdx.x * 2;

    #pragma unroll
    for (int pf = 0; pf < 2; pf++) {
        const uint32_t pb = sb + pf*34816;
        const uint32_t vb = sb + AP_VB + pf*18432;
        const uint32_t ab = sb + AP_AZB + pf*512;
        const int j0 = pf * 128;
        #pragma unroll
        for (int p = 0; p < 8; p++) {
            int idx = t + p*256; int row = idx >> 4, seg = idx & 15;
            cp16(pb + row*APITCH + seg*16, &g_pf16[((size_t)b*NN + j0 + row)*NN + i0 + seg*8]);
        }
        #pragma unroll
        for (int p = 0; p < 4; p++) {
            int idx = t + p*256; int row = idx >> 3, seg = idx & 7;
            cp16(vb + row*BPITCH + seg*16, &g_vf[(size_t)(b*NN + j0 + row)*CC + seg*8]);
        }
        if (t < 32)
            cp16(ab + t*16, &g_azh[(size_t)(b*64 + t0 + (t >> 4))*NN + j0 + (t & 15)*8]);
        CP_COMMIT();
    }

    float O[8][4];
    #pragma unroll
    for (int cn = 0; cn < 8; cn++)
        #pragma unroll
        for (int u = 0; u < 4; u++) O[cn][u] = 0.f;

    for (int jt = 0; jt < NN/128; jt++) {
        if (jt < NN/128 - 1) CP_WAIT1(); else CP_WAIT0();
        __syncthreads();

        const uint32_t pb = sb + (jt & 1)*34816;
        const uint32_t vb = sb + AP_VB + (jt & 1)*18432;
        const char* azp = smc + AP_AZB + (jt & 1)*512 + (w >> 2)*256;

        uint32_t A[8][4];
        #pragma unroll
        for (int ks = 0; ks < 8; ks++) {
            ldsm4t(addrAt(pb, w*16, ks*16, lr, g), A[ks]);
            uint32_t az01 = *(const uint32_t*)(azp + (ks*16 + 2*qc)*2);
            uint32_t az89 = *(const uint32_t*)(azp + (ks*16 + 2*qc + 8)*2);
            A[ks][0] = hmul2u(A[ks][0], az01);
            A[ks][1] = hmul2u(A[ks][1], az01);
            A[ks][2] = hmul2u(A[ks][2], az89);
            A[ks][3] = hmul2u(A[ks][3], az89);
        }
        #pragma unroll
        for (int cn = 0; cn < 8; cn++) {
            uint32_t vv[16];
            ldsm4t(addrBt(vb,  0, cn*8, lr, g), vv);
            ldsm4t(addrBt(vb, 32, cn*8, lr, g), vv + 4);
            ldsm4t(addrBt(vb, 64, cn*8, lr, g), vv + 8);
            ldsm4t(addrBt(vb, 96, cn*8, lr, g), vv + 12);
            #pragma unroll
            for (int ks = 0; ks < 8; ks++) mma16816h(O[cn], A[ks], vv[2*ks], vv[2*ks+1]);
        }
        __syncthreads();

        if (jt + 2 < NN/128) {
            const uint32_t dpb = sb + (jt & 1)*34816;
            const uint32_t dvb = sb + AP_VB + (jt & 1)*18432;
            const uint32_t dab = sb + AP_AZB + (jt & 1)*512;
            const int j0n = (jt + 2) * 128;
            #pragma unroll
            for (int p = 0; p < 8; p++) {
                int idx = t + p*256; int row = idx >> 4, seg = idx & 15;
                cp16(dpb + row*APITCH + seg*16, &g_pf16[((size_t)b*NN + j0n + row)*NN + i0 + seg*8]);
            }
            #pragma unroll
            for (int p = 0; p < 4; p++) {
                int idx = t + p*256; int row = idx >> 3, seg = idx & 7;
                cp16(dvb + row*BPITCH + seg*16, &g_vf[(size_t)(b*NN + j0n + row)*CC + seg*8]);
            }
            if (t < 32)
                cp16(dab + t*16, &g_azh[(size_t)(b*64 + t0 + (t >> 4))*NN + j0n + (t & 15)*8]);
            CP_COMMIT();
        }
    }

    // ---------- fused output projection ----------
    float* rstile = reinterpret_cast<float*>(smc);
    float* wst    = reinterpret_cast<float*>(smc + 34816);

    {
        const int ia0 = swapbits(w*16 + qr);
        const int ia1 = swapbits(w*16 + qr + 8);
        #pragma unroll
        for (int cn = 0; cn < 8; cn++) {
            const int col = cn*8 + qc*2;
            rstile[(col    )*RPITCH + ia0] = O[cn][0];
            rstile[(col + 1)*RPITCH + ia0] = O[cn][1];
            rstile[(col    )*RPITCH + ia1] = O[cn][2];
            rstile[(col + 1)*RPITCH + ia1] = O[cn][3];
        }
    }
    for (int idx = t; idx < CC*CC; idx += 256) {
        int cout = idx >> 6, cin = idx & 63;
        wst[cin*PITCH + cout] = Wo[idx];
    }
    __syncthreads();

    const int tx = t & 15, ty = t >> 4;
    #pragma unroll
    for (int h = 0; h < 2; h++) {
        float acc[4][4];
        #pragma unroll
        for (int k = 0; k < 4; k++)
            #pragma unroll
            for (int j = 0; j < 4; j++) acc[k][j] = 0.f;

        #pragma unroll 4
        for (int ci = 0; ci < CC; ci++) {
            const float4 r4 = LD4(&rstile[ci*RPITCH + h*64 + 4*tx]);
            float wv[4];
            #pragma unroll
            for (int k = 0; k < 4; k++) wv[k] = wst[ci*PITCH + ty + 16*k];
            #pragma unroll
            for (int k = 0; k < 4; k++) {
                acc[k][0] = fmaf(wv[k], r4.x, acc[k][0]);
                acc[k][1] = fmaf(wv[k], r4.y, acc[k][1]);
                acc[k][2] = fmaf(wv[k], r4.z, acc[k][2]);
                acc[k][3] = fmaf(wv[k], r4.w, acc[k][3]);
            }
        }

        #pragma unroll
        for (int k = 0; k < 4; k++) {
            const int c = ty + 16*k;
            const float bvv = bo[c];
            const float4 resid = LD4(&rstile[c*RPITCH + h*64 + 4*tx]);
            float4 o;
            o.x = acc[k][0] + bvv + resid.x;
            o.y = acc[k][1] + bvv + resid.y;
            o.z = acc[k][2] + bvv + resid.z;
            o.w = acc[k][3] + bvv + resid.w;
            *(float4*)&out[(size_t)(b*CC + c)*NN + i0 + h*64 + 4*tx] = o;
        }
    }
}

// ------------------------------------------------------------------
extern "C" void kernel_launch(void* const* d_in, const int* in_sizes, int n_in,
                              void* d_out, int out_size)
{
    const float* x  = (const float*)d_in[0];
    const float* Wq = (const float*)d_in[1];
    const float* bq = (const float*)d_in[2];
    const float* Wk = (const float*)d_in[3];
    const float* bk = (const float*)d_in[4];
    const float* Wv = (const float*)d_in[5];
    const float* bv = (const float*)d_in[6];
    const float* Wo = (const float*)d_in[7];
    const float* bo = (const float*)d_in[8];
    float* out = (float*)d_out;

    cudaFuncSetAttribute(qkv_kernel,   cudaFuncAttributeMaxDynamicSharedMemorySize, QKV_SMEM);
    cudaFuncSetAttribute(stats_kernel, cudaFuncAttributeMaxDynamicSharedMemorySize, ST_SMEM);
    cudaFuncSetAttribute(apply_kernel, cudaFuncAttributeMaxDynamicSharedMemorySize, AP_SMEM);

    qkv_kernel<<<dim3(NN/256, BB), 512, QKV_SMEM>>>(x, Wq, bq, Wk, bk, Wv, bv);
    stats_kernel<<<dim3(NN/128, BB), 256, ST_SMEM>>>();
    apply_kernel<<<dim3(NN/128, BB), 256, AP_SMEM>>>(Wo, bo, out);
}